// round 1
// baseline (speedup 1.0000x reference)
#include <cuda_runtime.h>
#include <math.h>

// Problem constants (fixed by the reference)
constexpr int M_TOK  = 65536;   // tokens
constexpr int DIMC   = 256;     // channels
constexpr int NHEAD  = 8;
constexpr int HD     = 32;      // head dim
constexpr int HIDDEN = 1024;
constexpr int NWIN   = 256;     // windows
constexpr int WTOK   = 256;     // tokens per window (4^4)

// Scratch (device globals: allocation-free rule)
__device__ float g_ln  [(size_t)M_TOK * DIMC];
__device__ float g_qkv [(size_t)M_TOK * 3 * DIMC];
__device__ float g_attn[(size_t)M_TOK * DIMC];
__device__ float g_x2  [(size_t)M_TOK * DIMC];
__device__ float g_mlp [(size_t)M_TOK * HIDDEN];

// Map window-ordered token r = wi*256+pos -> global token index in x
// (fuses roll(-2) + 4D window partition; same map inverts the output scatter)
__device__ __forceinline__ int src_index(int r) {
    int wi = r >> 8, pos = r & 255;
    int h1 = (wi >> 6) & 3, w1 = (wi >> 4) & 3, h2 = (wi >> 2) & 3, w2 = wi & 3;
    int a  = (pos >> 6) & 3, b  = (pos >> 4) & 3, c  = (pos >> 2) & 3, d  = pos & 3;
    int A_ = (h1 * 4 + a + 2) & 15;
    int B_ = (w1 * 4 + b + 2) & 15;
    int C_ = (h2 * 4 + c + 2) & 15;
    int D_ = (w2 * 4 + d + 2) & 15;
    return ((A_ * 16 + B_) * 16 + C_) * 16 + D_;
}

// ---------------- LayerNorm: one block per row, 256 threads ----------------
__global__ void __launch_bounds__(256) ln_kernel(
    const float* __restrict__ x, const float* __restrict__ g,
    const float* __restrict__ b, float* __restrict__ out)
{
    int row = blockIdx.x, t = threadIdx.x;
    float v = x[(size_t)row * DIMC + t];
    __shared__ float red[8];

    float s = v;
    #pragma unroll
    for (int o = 16; o; o >>= 1) s += __shfl_xor_sync(0xffffffffu, s, o);
    if ((t & 31) == 0) red[t >> 5] = s;
    __syncthreads();
    float tot = red[0] + red[1] + red[2] + red[3] + red[4] + red[5] + red[6] + red[7];
    float mu = tot * (1.0f / DIMC);
    __syncthreads();

    float dv = v - mu;
    s = dv * dv;
    #pragma unroll
    for (int o = 16; o; o >>= 1) s += __shfl_xor_sync(0xffffffffu, s, o);
    if ((t & 31) == 0) red[t >> 5] = s;
    __syncthreads();
    tot = red[0] + red[1] + red[2] + red[3] + red[4] + red[5] + red[6] + red[7];
    float rstd = rsqrtf(tot * (1.0f / DIMC) + 1e-5f);

    out[(size_t)row * DIMC + t] = dv * rstd * g[t] + b[t];
}

// ---------------- Tiled SGEMM: C = A @ Bw^T (+bias, mode epilogue) ----------
// A: (M_TOK x KDIM) row-major, Bw: (NCOLS x KDIM) row-major (torch weight layout)
// MODE 0: QKV   — gather A rows via src_index, plain store (stride NCOLS)
// MODE 1: PROJ  — scatter row to g=src_index(row), add residual res[g]
// MODE 2: FC1   — exact GELU epilogue
// MODE 3: FC2   — add residual res[row]
template<int KDIM, int NCOLS, int MODE>
__global__ void __launch_bounds__(256) gemm_kernel(
    const float* __restrict__ A, const float* __restrict__ Bw,
    const float* __restrict__ bias, const float* __restrict__ res,
    float* __restrict__ Cout)
{
    constexpr int BM = 128, BN = 128, BK = 16;
    __shared__ float As[BK][BM];
    __shared__ float Bs[BK][BN];

    const int t  = threadIdx.x;
    const int tx = t & 15;   // N direction (x8)
    const int ty = t >> 4;   // M direction (x8)
    const int m0 = blockIdx.y * BM;
    const int n0 = blockIdx.x * BN;

    float acc[8][8];
    #pragma unroll
    for (int i = 0; i < 8; i++)
        #pragma unroll
        for (int j = 0; j < 8; j++) acc[i][j] = 0.0f;

    for (int k0 = 0; k0 < KDIM; k0 += BK) {
        // Load A tile: 128 rows x 16 cols = 512 float4
        #pragma unroll
        for (int jj = 0; jj < 2; jj++) {
            int idx = jj * 256 + t;
            int m = idx >> 2, k4 = idx & 3;
            int grow = (MODE == 0) ? src_index(m0 + m) : (m0 + m);
            float4 v = *reinterpret_cast<const float4*>(A + (size_t)grow * KDIM + k0 + k4 * 4);
            As[k4 * 4 + 0][m] = v.x;
            As[k4 * 4 + 1][m] = v.y;
            As[k4 * 4 + 2][m] = v.z;
            As[k4 * 4 + 3][m] = v.w;
        }
        // Load B tile: 128 rows x 16 cols = 512 float4
        #pragma unroll
        for (int jj = 0; jj < 2; jj++) {
            int idx = jj * 256 + t;
            int n = idx >> 2, k4 = idx & 3;
            float4 v = *reinterpret_cast<const float4*>(Bw + (size_t)(n0 + n) * KDIM + k0 + k4 * 4);
            Bs[k4 * 4 + 0][n] = v.x;
            Bs[k4 * 4 + 1][n] = v.y;
            Bs[k4 * 4 + 2][n] = v.z;
            Bs[k4 * 4 + 3][n] = v.w;
        }
        __syncthreads();

        #pragma unroll
        for (int k = 0; k < BK; k++) {
            float a[8], bb[8];
            #pragma unroll
            for (int i = 0; i < 8; i++) a[i] = As[k][ty * 8 + i];
            #pragma unroll
            for (int j = 0; j < 8; j++) bb[j] = Bs[k][tx * 8 + j];
            #pragma unroll
            for (int i = 0; i < 8; i++)
                #pragma unroll
                for (int j = 0; j < 8; j++) acc[i][j] += a[i] * bb[j];
        }
        __syncthreads();
    }

    #pragma unroll
    for (int i = 0; i < 8; i++) {
        int row = m0 + ty * 8 + i;
        int grow = (MODE == 1) ? src_index(row) : row;
        #pragma unroll
        for (int j = 0; j < 8; j++) {
            int col = n0 + tx * 8 + j;
            float v = acc[i][j] + bias[col];
            if (MODE == 0) {
                Cout[(size_t)row * NCOLS + col] = v;
            } else if (MODE == 1) {
                Cout[(size_t)grow * DIMC + col] = res[(size_t)grow * DIMC + col] + v;
            } else if (MODE == 2) {
                Cout[(size_t)row * NCOLS + col] = 0.5f * v * (1.0f + erff(v * 0.70710678118654752f));
            } else {
                Cout[(size_t)row * NCOLS + col] = res[(size_t)row * DIMC + col] + v;
            }
        }
    }
}

// ---------------- Windowed attention: block = (window, head) ----------------
// 8 warps, each warp handles 32 query rows. K/V in smem (stride 33 = conflict-free
// in both QK^T phase (lane varies m) and PV phase (lane varies d)).
__global__ void __launch_bounds__(256) attn_kernel(
    const float* __restrict__ qkv, const float* __restrict__ bias_table,
    const float* __restrict__ mask, const int* __restrict__ rel,
    float* __restrict__ out)
{
    extern __shared__ float sm[];
    float* ks = sm;               // 256*33
    float* vs = ks + 256 * 33;    // 256*33
    float* qs = vs + 256 * 33;    // 8*32
    float* ps = qs + 8 * 32;      // 8*256

    const int wi = blockIdx.x, h = blockIdx.y;
    const int t = threadIdx.x, lane = t & 31, warp = t >> 5;
    const float* base = qkv + (size_t)wi * WTOK * 768;
    const float* maskb = mask + (size_t)wi * WTOK * WTOK;
    const float scale = 0.17677669529663687f;  // 32^-0.5

    // Load K and V for this (window, head)
    for (int idx = t; idx < WTOK * HD; idx += 256) {
        int m = idx >> 5, d = idx & 31;
        ks[m * 33 + d] = base[(size_t)m * 768 + 256 + h * 32 + d];
        vs[m * 33 + d] = base[(size_t)m * 768 + 512 + h * 32 + d];
    }
    __syncthreads();

    for (int n = warp; n < WTOK; n += 8) {
        // load q row into per-warp smem (broadcast reads in dot loop)
        qs[warp * 32 + lane] = base[(size_t)n * 768 + h * 32 + lane] * scale;
        __syncwarp();

        float s[8];
        #pragma unroll
        for (int j = 0; j < 8; j++) {
            int m = j * 32 + lane;
            float a = 0.0f;
            #pragma unroll
            for (int d = 0; d < 32; d++) a += qs[warp * 32 + d] * ks[m * 33 + d];
            int ri = rel[n * WTOK + m];
            a += bias_table[ri * NHEAD + h] + maskb[n * WTOK + m];
            s[j] = a;
        }

        // softmax over 256 values (8 per lane)
        float mx = s[0];
        #pragma unroll
        for (int j = 1; j < 8; j++) mx = fmaxf(mx, s[j]);
        #pragma unroll
        for (int o = 16; o; o >>= 1) mx = fmaxf(mx, __shfl_xor_sync(0xffffffffu, mx, o));
        float sum = 0.0f;
        #pragma unroll
        for (int j = 0; j < 8; j++) { s[j] = expf(s[j] - mx); sum += s[j]; }
        #pragma unroll
        for (int o = 16; o; o >>= 1) sum += __shfl_xor_sync(0xffffffffu, sum, o);
        float inv = 1.0f / sum;

        #pragma unroll
        for (int j = 0; j < 8; j++) ps[warp * 256 + j * 32 + lane] = s[j] * inv;
        __syncwarp();

        // out[d=lane] = sum_m p[m] * v[m][lane]
        float o = 0.0f;
        #pragma unroll 8
        for (int m = 0; m < WTOK; m++) o += ps[warp * 256 + m] * vs[m * 33 + lane];
        out[((size_t)wi * WTOK + n) * DIMC + h * 32 + lane] = o;
        __syncwarp();
    }
}

// ---------------- launch ----------------
extern "C" void kernel_launch(void* const* d_in, const int* in_sizes, int n_in,
                              void* d_out, int out_size)
{
    const float* x          = (const float*)d_in[0];
    const float* g1         = (const float*)d_in[1];
    const float* b1         = (const float*)d_in[2];
    const float* qkv_w      = (const float*)d_in[3];
    const float* qkv_b      = (const float*)d_in[4];
    const float* bias_table = (const float*)d_in[5];
    const float* proj_w     = (const float*)d_in[6];
    const float* proj_b     = (const float*)d_in[7];
    const float* g2         = (const float*)d_in[8];
    const float* b2         = (const float*)d_in[9];
    const float* fc1_w      = (const float*)d_in[10];
    const float* fc1_b      = (const float*)d_in[11];
    const float* fc2_w      = (const float*)d_in[12];
    const float* fc2_b      = (const float*)d_in[13];
    const float* attn_mask  = (const float*)d_in[14];
    const int*   rel_index  = (const int*)d_in[15];
    float* out = (float*)d_out;

    float *p_ln, *p_qkv, *p_attn, *p_x2, *p_mlp;
    cudaGetSymbolAddress((void**)&p_ln,   g_ln);
    cudaGetSymbolAddress((void**)&p_qkv,  g_qkv);
    cudaGetSymbolAddress((void**)&p_attn, g_attn);
    cudaGetSymbolAddress((void**)&p_x2,   g_x2);
    cudaGetSymbolAddress((void**)&p_mlp,  g_mlp);

    const int ATTN_SMEM = (256 * 33 * 2 + 8 * 32 + 8 * 256) * 4;  // 76800
    cudaFuncSetAttribute(attn_kernel, cudaFuncAttributeMaxDynamicSharedMemorySize, ATTN_SMEM);

    // LN1
    ln_kernel<<<M_TOK, 256>>>(x, g1, b1, p_ln);
    // QKV (gathered rows => window order)
    gemm_kernel<256, 768, 0><<<dim3(768 / 128, M_TOK / 128), 256>>>(p_ln, qkv_w, qkv_b, nullptr, p_qkv);
    // attention
    attn_kernel<<<dim3(NWIN, NHEAD), 256, ATTN_SMEM>>>(p_qkv, bias_table, attn_mask, rel_index, p_attn);
    // proj + window-reverse scatter + shortcut
    gemm_kernel<256, 256, 1><<<dim3(256 / 128, M_TOK / 128), 256>>>(p_attn, proj_w, proj_b, x, p_x2);
    // LN2
    ln_kernel<<<M_TOK, 256>>>(p_x2, g2, b2, p_ln);
    // fc1 + GELU
    gemm_kernel<256, 1024, 2><<<dim3(1024 / 128, M_TOK / 128), 256>>>(p_ln, fc1_w, fc1_b, nullptr, p_mlp);
    // fc2 + residual
    gemm_kernel<1024, 256, 3><<<dim3(256 / 128, M_TOK / 128), 256>>>(p_mlp, fc2_w, fc2_b, p_x2, out);
}

// round 3
// speedup vs baseline: 1.7308x; 1.7308x over previous
#include <cuda_runtime.h>
#include <cstdint>
#include <math.h>

// Problem constants
constexpr int M_TOK  = 65536;
constexpr int DIMC   = 256;
constexpr int NHEAD  = 8;
constexpr int HD     = 32;
constexpr int HIDDEN = 1024;
constexpr int NWIN   = 256;
constexpr int WTOK   = 256;

// Scratch
__device__ float g_ln  [(size_t)M_TOK * DIMC];
__device__ float g_qkv [(size_t)M_TOK * 3 * DIMC];
__device__ float g_attn[(size_t)M_TOK * DIMC];
__device__ float g_x2  [(size_t)M_TOK * DIMC];
__device__ float g_mlp [(size_t)M_TOK * HIDDEN];

// ---------------- helpers ----------------
__device__ __forceinline__ uint32_t smem_u32(const void* p) {
    uint32_t a;
    asm("{ .reg .u64 t; cvta.to.shared.u64 t, %1; cvt.u32.u64 %0, t; }" : "=r"(a) : "l"(p));
    return a;
}
__device__ __forceinline__ uint32_t cvt_tf32(float f) {
    uint32_t u;
    asm("cvt.rna.tf32.f32 %0, %1;" : "=r"(u) : "f"(f));
    return u;
}
__device__ __forceinline__ void sts128(uint32_t addr, uint32_t a, uint32_t b, uint32_t c, uint32_t d) {
    asm volatile("st.shared.v4.b32 [%0], {%1,%2,%3,%4};" :: "r"(addr), "r"(a), "r"(b), "r"(c), "r"(d));
}
__device__ __forceinline__ void ldsm4(uint32_t addr, uint32_t& r0, uint32_t& r1, uint32_t& r2, uint32_t& r3) {
    asm volatile("ldmatrix.sync.aligned.m8n8.x4.shared.b16 {%0,%1,%2,%3}, [%4];"
                 : "=r"(r0), "=r"(r1), "=r"(r2), "=r"(r3) : "r"(addr));
}
__device__ __forceinline__ void ldsm2(uint32_t addr, uint32_t& r0, uint32_t& r1) {
    asm volatile("ldmatrix.sync.aligned.m8n8.x2.shared.b16 {%0,%1}, [%2];"
                 : "=r"(r0), "=r"(r1) : "r"(addr));
}
__device__ __forceinline__ void mma_tf32(float c[4], uint32_t a0, uint32_t a1, uint32_t a2, uint32_t a3,
                                         uint32_t b0, uint32_t b1) {
    asm volatile("mma.sync.aligned.m16n8k8.row.col.f32.tf32.tf32.f32 "
                 "{%0,%1,%2,%3}, {%4,%5,%6,%7}, {%8,%9}, {%0,%1,%2,%3};"
                 : "+f"(c[0]), "+f"(c[1]), "+f"(c[2]), "+f"(c[3])
                 : "r"(a0), "r"(a1), "r"(a2), "r"(a3), "r"(b0), "r"(b1));
}

// roll(-2)+window-partition row map (bijection; also the output scatter)
__device__ __forceinline__ int src_index(int r) {
    int wi = r >> 8, pos = r & 255;
    int h1 = (wi >> 6) & 3, w1 = (wi >> 4) & 3, h2 = (wi >> 2) & 3, w2 = wi & 3;
    int a  = (pos >> 6) & 3, b  = (pos >> 4) & 3, c  = (pos >> 2) & 3, d  = pos & 3;
    int A_ = (h1 * 4 + a + 2) & 15;
    int B_ = (w1 * 4 + b + 2) & 15;
    int C_ = (h2 * 4 + c + 2) & 15;
    int D_ = (w2 * 4 + d + 2) & 15;
    return ((A_ * 16 + B_) * 16 + C_) * 16 + D_;
}

// ---------------- LayerNorm ----------------
__global__ void __launch_bounds__(256) ln_kernel(
    const float* __restrict__ x, const float* __restrict__ g,
    const float* __restrict__ b, float* __restrict__ out)
{
    int row = blockIdx.x, t = threadIdx.x;
    float v = x[(size_t)row * DIMC + t];
    __shared__ float red[8];
    float s = v;
    #pragma unroll
    for (int o = 16; o; o >>= 1) s += __shfl_xor_sync(0xffffffffu, s, o);
    if ((t & 31) == 0) red[t >> 5] = s;
    __syncthreads();
    float tot = red[0]+red[1]+red[2]+red[3]+red[4]+red[5]+red[6]+red[7];
    float mu = tot * (1.0f / DIMC);
    __syncthreads();
    float dv = v - mu;
    s = dv * dv;
    #pragma unroll
    for (int o = 16; o; o >>= 1) s += __shfl_xor_sync(0xffffffffu, s, o);
    if ((t & 31) == 0) red[t >> 5] = s;
    __syncthreads();
    tot = red[0]+red[1]+red[2]+red[3]+red[4]+red[5]+red[6]+red[7];
    float rstd = rsqrtf(tot * (1.0f / DIMC) + 1e-5f);
    out[(size_t)row * DIMC + t] = dv * rstd * g[t] + b[t];
}

// ---------------- tf32 mma.sync GEMM: C = A @ Bw^T (+bias, epilogue) -------
// MODE 0: QKV (gather A rows)   MODE 1: proj (scatter + residual)
// MODE 2: fc1 (+exact GELU)     MODE 3: fc2 (+residual)
// Block 128x128xBK32, 8 warps (2M x 4N), warp tile 64x32, double-buffered smem.
// smem: As[2] @ 0 (16KB each), Bs[2] @ 32768 (16KB each); total 64KB.
template<int KDIM, int NCOLS, int MODE>
__global__ void __launch_bounds__(256) gemm_mma(
    const float* __restrict__ A, const float* __restrict__ Bw,
    const float* __restrict__ bias, const float* __restrict__ res,
    float* __restrict__ Cout)
{
    extern __shared__ char sm[];
    const uint32_t smb = smem_u32(sm);
    const int t = threadIdx.x, lane = t & 31, warp = t >> 5;
    const int wm = warp & 1, wn = warp >> 1;
    const int m0 = blockIdx.y * 128, n0 = blockIdx.x * 128;
    constexpr int NC = KDIM / 32;

    // Copy-thread geometry: idx = i*256+t -> (row = idx>>3, u = idx&7) 16B chunk
    const float* aptr[4];
    const float* bptr[4];
    uint32_t sA[4], sB[4];
    #pragma unroll
    for (int i = 0; i < 4; i++) {
        int idx = i * 256 + t;
        int row = idx >> 3, u = idx & 7;
        int gr = (MODE == 0) ? src_index(m0 + row) : (m0 + row);
        aptr[i] = A  + (size_t)gr * KDIM + u * 4;
        bptr[i] = Bw + (size_t)(n0 + row) * KDIM + u * 4;
        uint32_t off = row * 128 + ((u ^ (row & 7)) << 4);
        sA[i] = smb + off;
        sB[i] = smb + 32768 + off;
    }

    float4 apf[4], bpf[4];
    #pragma unroll
    for (int i = 0; i < 4; i++) {
        apf[i] = *reinterpret_cast<const float4*>(aptr[i]);
        bpf[i] = *reinterpret_cast<const float4*>(bptr[i]);
    }

    float acc[4][4][4];
    #pragma unroll
    for (int ms = 0; ms < 4; ms++)
        #pragma unroll
        for (int ns = 0; ns < 4; ns++)
            #pragma unroll
            for (int r = 0; r < 4; r++) acc[ms][ns][r] = 0.0f;

    for (int ch = 0; ch < NC; ch++) {
        const uint32_t bofs = (ch & 1) * 16384;
        #pragma unroll
        for (int i = 0; i < 4; i++) {
            sts128(sA[i] + bofs, cvt_tf32(apf[i].x), cvt_tf32(apf[i].y), cvt_tf32(apf[i].z), cvt_tf32(apf[i].w));
            sts128(sB[i] + bofs, cvt_tf32(bpf[i].x), cvt_tf32(bpf[i].y), cvt_tf32(bpf[i].z), cvt_tf32(bpf[i].w));
        }
        __syncthreads();

        if (ch + 1 < NC) {
            #pragma unroll
            for (int i = 0; i < 4; i++) {
                apf[i] = *reinterpret_cast<const float4*>(aptr[i] + (ch + 1) * 32);
                bpf[i] = *reinterpret_cast<const float4*>(bptr[i] + (ch + 1) * 32);
            }
        }

        const uint32_t abase = smb + bofs;
        const uint32_t bbase = smb + 32768 + bofs;
        const int rlA = lane & 15;
        #pragma unroll
        for (int ks = 0; ks < 4; ks++) {
            uint32_t af[4][4];
            #pragma unroll
            for (int ms = 0; ms < 4; ms++) {
                int r = wm * 64 + ms * 16 + rlA;
                int cch = 2 * ks + (lane >> 4);
                ldsm4(abase + r * 128 + ((cch ^ (r & 7)) << 4), af[ms][0], af[ms][1], af[ms][2], af[ms][3]);
            }
            uint32_t bf[4][2];
            #pragma unroll
            for (int ns = 0; ns < 4; ns++) {
                int r = wn * 32 + ns * 8 + (lane & 7);
                int cch = 2 * ks + ((lane >> 3) & 1);
                ldsm2(bbase + r * 128 + ((cch ^ (r & 7)) << 4), bf[ns][0], bf[ns][1]);
            }
            #pragma unroll
            for (int ms = 0; ms < 4; ms++)
                #pragma unroll
                for (int ns = 0; ns < 4; ns++)
                    mma_tf32(acc[ms][ns], af[ms][0], af[ms][1], af[ms][2], af[ms][3], bf[ns][0], bf[ns][1]);
        }
        __syncthreads();
    }

    // Epilogue: c0:(g,2c) c1:(g,2c+1) c2:(g+8,2c) c3:(g+8,2c+1)
    const int g = lane >> 2, tig = lane & 3;
    #pragma unroll
    for (int ms = 0; ms < 4; ms++) {
        int row0 = m0 + wm * 64 + ms * 16 + g;
        int row1 = row0 + 8;
        int or0 = (MODE == 1) ? src_index(row0) : row0;
        int or1 = (MODE == 1) ? src_index(row1) : row1;
        #pragma unroll
        for (int ns = 0; ns < 4; ns++) {
            int col = n0 + wn * 32 + ns * 8 + 2 * tig;
            float bx = bias[col], by = bias[col + 1];
            float v0x = acc[ms][ns][0] + bx, v0y = acc[ms][ns][1] + by;
            float v1x = acc[ms][ns][2] + bx, v1y = acc[ms][ns][3] + by;
            if (MODE == 1) {
                float2 r0 = *reinterpret_cast<const float2*>(res + (size_t)or0 * DIMC + col);
                float2 r1 = *reinterpret_cast<const float2*>(res + (size_t)or1 * DIMC + col);
                *reinterpret_cast<float2*>(Cout + (size_t)or0 * DIMC + col) = make_float2(v0x + r0.x, v0y + r0.y);
                *reinterpret_cast<float2*>(Cout + (size_t)or1 * DIMC + col) = make_float2(v1x + r1.x, v1y + r1.y);
            } else if (MODE == 2) {
                v0x = 0.5f * v0x * (1.0f + erff(v0x * 0.70710678118654752f));
                v0y = 0.5f * v0y * (1.0f + erff(v0y * 0.70710678118654752f));
                v1x = 0.5f * v1x * (1.0f + erff(v1x * 0.70710678118654752f));
                v1y = 0.5f * v1y * (1.0f + erff(v1y * 0.70710678118654752f));
                *reinterpret_cast<float2*>(Cout + (size_t)row0 * NCOLS + col) = make_float2(v0x, v0y);
                *reinterpret_cast<float2*>(Cout + (size_t)row1 * NCOLS + col) = make_float2(v1x, v1y);
            } else if (MODE == 3) {
                float2 r0 = *reinterpret_cast<const float2*>(res + (size_t)row0 * DIMC + col);
                float2 r1 = *reinterpret_cast<const float2*>(res + (size_t)row1 * DIMC + col);
                *reinterpret_cast<float2*>(Cout + (size_t)row0 * NCOLS + col) = make_float2(v0x + r0.x, v0y + r0.y);
                *reinterpret_cast<float2*>(Cout + (size_t)row1 * NCOLS + col) = make_float2(v1x + r1.x, v1y + r1.y);
            } else {
                *reinterpret_cast<float2*>(Cout + (size_t)row0 * NCOLS + col) = make_float2(v0x, v0y);
                *reinterpret_cast<float2*>(Cout + (size_t)row1 * NCOLS + col) = make_float2(v1x, v1y);
            }
        }
    }
}

// ---------------- Windowed attention (unchanged from R1) ----------------
__global__ void __launch_bounds__(256) attn_kernel(
    const float* __restrict__ qkv, const float* __restrict__ bias_table,
    const float* __restrict__ mask, const int* __restrict__ rel,
    float* __restrict__ out)
{
    extern __shared__ float smf[];
    float* ks = smf;
    float* vs = ks + 256 * 33;
    float* qs = vs + 256 * 33;
    float* ps = qs + 8 * 32;

    const int wi = blockIdx.x, h = blockIdx.y;
    const int t = threadIdx.x, lane = t & 31, warp = t >> 5;
    const float* base = qkv + (size_t)wi * WTOK * 768;
    const float* maskb = mask + (size_t)wi * WTOK * WTOK;
    const float scale = 0.17677669529663687f;

    for (int idx = t; idx < WTOK * HD; idx += 256) {
        int m = idx >> 5, d = idx & 31;
        ks[m * 33 + d] = base[(size_t)m * 768 + 256 + h * 32 + d];
        vs[m * 33 + d] = base[(size_t)m * 768 + 512 + h * 32 + d];
    }
    __syncthreads();

    for (int n = warp; n < WTOK; n += 8) {
        qs[warp * 32 + lane] = base[(size_t)n * 768 + h * 32 + lane] * scale;
        __syncwarp();
        float s[8];
        #pragma unroll
        for (int j = 0; j < 8; j++) {
            int m = j * 32 + lane;
            float a = 0.0f;
            #pragma unroll
            for (int d = 0; d < 32; d++) a += qs[warp * 32 + d] * ks[m * 33 + d];
            int ri = rel[n * WTOK + m];
            a += bias_table[ri * NHEAD + h] + maskb[n * WTOK + m];
            s[j] = a;
        }
        float mx = s[0];
        #pragma unroll
        for (int j = 1; j < 8; j++) mx = fmaxf(mx, s[j]);
        #pragma unroll
        for (int o = 16; o; o >>= 1) mx = fmaxf(mx, __shfl_xor_sync(0xffffffffu, mx, o));
        float sum = 0.0f;
        #pragma unroll
        for (int j = 0; j < 8; j++) { s[j] = expf(s[j] - mx); sum += s[j]; }
        #pragma unroll
        for (int o = 16; o; o >>= 1) sum += __shfl_xor_sync(0xffffffffu, sum, o);
        float inv = 1.0f / sum;
        #pragma unroll
        for (int j = 0; j < 8; j++) ps[warp * 256 + j * 32 + lane] = s[j] * inv;
        __syncwarp();
        float o = 0.0f;
        #pragma unroll 8
        for (int m = 0; m < WTOK; m++) o += ps[warp * 256 + m] * vs[m * 33 + lane];
        out[((size_t)wi * WTOK + n) * DIMC + h * 32 + lane] = o;
        __syncwarp();
    }
}

// ---------------- launch ----------------
extern "C" void kernel_launch(void* const* d_in, const int* in_sizes, int n_in,
                              void* d_out, int out_size)
{
    const float* x          = (const float*)d_in[0];
    const float* g1         = (const float*)d_in[1];
    const float* b1         = (const float*)d_in[2];
    const float* qkv_w      = (const float*)d_in[3];
    const float* qkv_b      = (const float*)d_in[4];
    const float* bias_table = (const float*)d_in[5];
    const float* proj_w     = (const float*)d_in[6];
    const float* proj_b     = (const float*)d_in[7];
    const float* g2         = (const float*)d_in[8];
    const float* b2         = (const float*)d_in[9];
    const float* fc1_w      = (const float*)d_in[10];
    const float* fc1_b      = (const float*)d_in[11];
    const float* fc2_w      = (const float*)d_in[12];
    const float* fc2_b      = (const float*)d_in[13];
    const float* attn_mask  = (const float*)d_in[14];
    const int*   rel_index  = (const int*)d_in[15];
    float* out = (float*)d_out;

    float *p_ln, *p_qkv, *p_attn, *p_x2, *p_mlp;
    cudaGetSymbolAddress((void**)&p_ln,   g_ln);
    cudaGetSymbolAddress((void**)&p_qkv,  g_qkv);
    cudaGetSymbolAddress((void**)&p_attn, g_attn);
    cudaGetSymbolAddress((void**)&p_x2,   g_x2);
    cudaGetSymbolAddress((void**)&p_mlp,  g_mlp);

    const int GEMM_SMEM = 65536;
    cudaFuncSetAttribute((const void*)gemm_mma<256, 768, 0>,  cudaFuncAttributeMaxDynamicSharedMemorySize, GEMM_SMEM);
    cudaFuncSetAttribute((const void*)gemm_mma<256, 256, 1>,  cudaFuncAttributeMaxDynamicSharedMemorySize, GEMM_SMEM);
    cudaFuncSetAttribute((const void*)gemm_mma<256, 1024, 2>, cudaFuncAttributeMaxDynamicSharedMemorySize, GEMM_SMEM);
    cudaFuncSetAttribute((const void*)gemm_mma<1024, 256, 3>, cudaFuncAttributeMaxDynamicSharedMemorySize, GEMM_SMEM);

    const int ATTN_SMEM = (256 * 33 * 2 + 8 * 32 + 8 * 256) * 4;
    cudaFuncSetAttribute(attn_kernel, cudaFuncAttributeMaxDynamicSharedMemorySize, ATTN_SMEM);

    ln_kernel<<<M_TOK, 256>>>(x, g1, b1, p_ln);
    gemm_mma<256, 768, 0><<<dim3(6, 512), 256, GEMM_SMEM>>>(p_ln, qkv_w, qkv_b, nullptr, p_qkv);
    attn_kernel<<<dim3(NWIN, NHEAD), 256, ATTN_SMEM>>>(p_qkv, bias_table, attn_mask, rel_index, p_attn);
    gemm_mma<256, 256, 1><<<dim3(2, 512), 256, GEMM_SMEM>>>(p_attn, proj_w, proj_b, x, p_x2);
    ln_kernel<<<M_TOK, 256>>>(p_x2, g2, b2, p_ln);
    gemm_mma<256, 1024, 2><<<dim3(8, 512), 256, GEMM_SMEM>>>(p_ln, fc1_w, fc1_b, nullptr, p_mlp);
    gemm_mma<1024, 256, 3><<<dim3(2, 512), 256, GEMM_SMEM>>>(p_mlp, fc2_w, fc2_b, p_x2, out);
}

// round 4
// speedup vs baseline: 3.9506x; 2.2825x over previous
#include <cuda_runtime.h>
#include <cstdint>
#include <math.h>

// Problem constants
constexpr int M_TOK  = 65536;
constexpr int DIMC   = 256;
constexpr int NHEAD  = 8;
constexpr int HIDDEN = 1024;
constexpr int NWIN   = 256;
constexpr int WTOK   = 256;

// Scratch
__device__ float g_ln  [(size_t)M_TOK * DIMC];
__device__ float g_qkv [(size_t)M_TOK * 3 * DIMC];
__device__ float g_attn[(size_t)M_TOK * DIMC];
__device__ float g_x2  [(size_t)M_TOK * DIMC];
__device__ float g_mlp [(size_t)M_TOK * HIDDEN];
__device__ float g_bias[(size_t)NHEAD * WTOK * WTOK];   // biasT[h][n][m]

// ---------------- helpers ----------------
__device__ __forceinline__ uint32_t smem_u32(const void* p) {
    uint32_t a;
    asm("{ .reg .u64 t; cvta.to.shared.u64 t, %1; cvt.u32.u64 %0, t; }" : "=r"(a) : "l"(p));
    return a;
}
__device__ __forceinline__ void cp_async16(uint32_t dst, const void* src) {
    asm volatile("cp.async.cg.shared.global [%0], [%1], 16;" :: "r"(dst), "l"(src));
}
#define CP_COMMIT() asm volatile("cp.async.commit_group;")
#define CP_WAIT(n)  asm volatile("cp.async.wait_group %0;" :: "n"(n))
__device__ __forceinline__ void ldsm4(uint32_t addr, uint32_t& r0, uint32_t& r1, uint32_t& r2, uint32_t& r3) {
    asm volatile("ldmatrix.sync.aligned.m8n8.x4.shared.b16 {%0,%1,%2,%3}, [%4];"
                 : "=r"(r0), "=r"(r1), "=r"(r2), "=r"(r3) : "r"(addr));
}
__device__ __forceinline__ void ldsm2(uint32_t addr, uint32_t& r0, uint32_t& r1) {
    asm volatile("ldmatrix.sync.aligned.m8n8.x2.shared.b16 {%0,%1}, [%2];"
                 : "=r"(r0), "=r"(r1) : "r"(addr));
}
__device__ __forceinline__ void mma_tf32(float c[4], uint32_t a0, uint32_t a1, uint32_t a2, uint32_t a3,
                                         uint32_t b0, uint32_t b1) {
    asm volatile("mma.sync.aligned.m16n8k8.row.col.f32.tf32.tf32.f32 "
                 "{%0,%1,%2,%3}, {%4,%5,%6,%7}, {%8,%9}, {%0,%1,%2,%3};"
                 : "+f"(c[0]), "+f"(c[1]), "+f"(c[2]), "+f"(c[3])
                 : "r"(a0), "r"(a1), "r"(a2), "r"(a3), "r"(b0), "r"(b1));
}

// roll(-2)+window-partition row map (bijection; also the output scatter)
__device__ __forceinline__ int src_index(int r) {
    int wi = r >> 8, pos = r & 255;
    int h1 = (wi >> 6) & 3, w1 = (wi >> 4) & 3, h2 = (wi >> 2) & 3, w2 = wi & 3;
    int a  = (pos >> 6) & 3, b  = (pos >> 4) & 3, c  = (pos >> 2) & 3, d  = pos & 3;
    int A_ = (h1 * 4 + a + 2) & 15;
    int B_ = (w1 * 4 + b + 2) & 15;
    int C_ = (h2 * 4 + c + 2) & 15;
    int D_ = (w2 * 4 + d + 2) & 15;
    return ((A_ * 16 + B_) * 16 + C_) * 16 + D_;
}

// ---------------- LayerNorm ----------------
__global__ void __launch_bounds__(256) ln_kernel(
    const float* __restrict__ x, const float* __restrict__ g,
    const float* __restrict__ b, float* __restrict__ out)
{
    int row = blockIdx.x, t = threadIdx.x;
    float v = x[(size_t)row * DIMC + t];
    __shared__ float red[8];
    float s = v;
    #pragma unroll
    for (int o = 16; o; o >>= 1) s += __shfl_xor_sync(0xffffffffu, s, o);
    if ((t & 31) == 0) red[t >> 5] = s;
    __syncthreads();
    float tot = red[0]+red[1]+red[2]+red[3]+red[4]+red[5]+red[6]+red[7];
    float mu = tot * (1.0f / DIMC);
    __syncthreads();
    float dv = v - mu;
    s = dv * dv;
    #pragma unroll
    for (int o = 16; o; o >>= 1) s += __shfl_xor_sync(0xffffffffu, s, o);
    if ((t & 31) == 0) red[t >> 5] = s;
    __syncthreads();
    tot = red[0]+red[1]+red[2]+red[3]+red[4]+red[5]+red[6]+red[7];
    float rstd = rsqrtf(tot * (1.0f / DIMC) + 1e-5f);
    out[(size_t)row * DIMC + t] = dv * rstd * g[t] + b[t];
}

// ---------------- biasT gather: biasT[h][n][m] = table[rel[n,m]][h] --------
__global__ void __launch_bounds__(256) biasT_kernel(
    const float* __restrict__ table, const int* __restrict__ rel, float* __restrict__ biasT)
{
    int nm = blockIdx.x * 256 + threadIdx.x;
    int ri = rel[nm];
    #pragma unroll
    for (int h = 0; h < 8; h++)
        biasT[(size_t)h * 65536 + nm] = table[ri * 8 + h];
}

// ---------------- tf32 mma.sync GEMM with cp.async double buffer ----------
// MODE 0: QKV (gather A rows)   MODE 1: proj (scatter + residual)
// MODE 2: fc1 (+exact GELU)     MODE 3: fc2 (+residual)
template<int KDIM, int NCOLS, int MODE>
__global__ void __launch_bounds__(256, 2) gemm_mma(
    const float* __restrict__ A, const float* __restrict__ Bw,
    const float* __restrict__ bias, const float* __restrict__ res,
    float* __restrict__ Cout)
{
    extern __shared__ char sm[];
    const uint32_t smb = smem_u32(sm);
    const int t = threadIdx.x, lane = t & 31, warp = t >> 5;
    const int wm = warp & 1, wn = warp >> 1;
    const int m0 = blockIdx.y * 128, n0 = blockIdx.x * 128;
    constexpr int NC = KDIM / 32;

    const float* aptr[4];
    const float* bptr[4];
    uint32_t sA[4], sB[4];
    #pragma unroll
    for (int i = 0; i < 4; i++) {
        int idx = i * 256 + t;
        int row = idx >> 3, u = idx & 7;
        int gr = (MODE == 0) ? src_index(m0 + row) : (m0 + row);
        aptr[i] = A  + (size_t)gr * KDIM + u * 4;
        bptr[i] = Bw + (size_t)(n0 + row) * KDIM + u * 4;
        uint32_t off = row * 128 + ((u ^ (row & 7)) << 4);
        sA[i] = smb + off;
        sB[i] = smb + 32768 + off;
    }

    // prologue: stage 0
    #pragma unroll
    for (int i = 0; i < 4; i++) {
        cp_async16(sA[i], aptr[i]);
        cp_async16(sB[i], bptr[i]);
    }
    CP_COMMIT();

    float acc[4][4][4];
    #pragma unroll
    for (int ms = 0; ms < 4; ms++)
        #pragma unroll
        for (int ns = 0; ns < 4; ns++)
            #pragma unroll
            for (int r = 0; r < 4; r++) acc[ms][ns][r] = 0.0f;

    for (int ch = 0; ch < NC; ch++) {
        const uint32_t bofs = (ch & 1) * 16384;
        if (ch + 1 < NC) {
            const uint32_t nofs = ((ch + 1) & 1) * 16384;
            #pragma unroll
            for (int i = 0; i < 4; i++) {
                cp_async16(sA[i] + nofs, aptr[i] + (ch + 1) * 32);
                cp_async16(sB[i] + nofs, bptr[i] + (ch + 1) * 32);
            }
            CP_COMMIT();
            CP_WAIT(1);
        } else {
            CP_WAIT(0);
        }
        __syncthreads();

        const uint32_t abase = smb + bofs;
        const uint32_t bbase = smb + 32768 + bofs;
        const int rlA = lane & 15;
        #pragma unroll
        for (int ks = 0; ks < 4; ks++) {
            uint32_t af[4][4];
            #pragma unroll
            for (int ms = 0; ms < 4; ms++) {
                int r = wm * 64 + ms * 16 + rlA;
                int cch = 2 * ks + (lane >> 4);
                ldsm4(abase + r * 128 + ((cch ^ (r & 7)) << 4), af[ms][0], af[ms][1], af[ms][2], af[ms][3]);
            }
            uint32_t bf[4][2];
            #pragma unroll
            for (int ns = 0; ns < 4; ns++) {
                int r = wn * 32 + ns * 8 + (lane & 7);
                int cch = 2 * ks + ((lane >> 3) & 1);
                ldsm2(bbase + r * 128 + ((cch ^ (r & 7)) << 4), bf[ns][0], bf[ns][1]);
            }
            #pragma unroll
            for (int ms = 0; ms < 4; ms++)
                #pragma unroll
                for (int ns = 0; ns < 4; ns++)
                    mma_tf32(acc[ms][ns], af[ms][0], af[ms][1], af[ms][2], af[ms][3], bf[ns][0], bf[ns][1]);
        }
        __syncthreads();
    }

    const int g = lane >> 2, tig = lane & 3;
    #pragma unroll
    for (int ms = 0; ms < 4; ms++) {
        int row0 = m0 + wm * 64 + ms * 16 + g;
        int row1 = row0 + 8;
        int or0 = (MODE == 1) ? src_index(row0) : row0;
        int or1 = (MODE == 1) ? src_index(row1) : row1;
        #pragma unroll
        for (int ns = 0; ns < 4; ns++) {
            int col = n0 + wn * 32 + ns * 8 + 2 * tig;
            float bx = bias[col], by = bias[col + 1];
            float v0x = acc[ms][ns][0] + bx, v0y = acc[ms][ns][1] + by;
            float v1x = acc[ms][ns][2] + bx, v1y = acc[ms][ns][3] + by;
            if (MODE == 1) {
                float2 r0 = *reinterpret_cast<const float2*>(res + (size_t)or0 * DIMC + col);
                float2 r1 = *reinterpret_cast<const float2*>(res + (size_t)or1 * DIMC + col);
                *reinterpret_cast<float2*>(Cout + (size_t)or0 * DIMC + col) = make_float2(v0x + r0.x, v0y + r0.y);
                *reinterpret_cast<float2*>(Cout + (size_t)or1 * DIMC + col) = make_float2(v1x + r1.x, v1y + r1.y);
            } else if (MODE == 2) {
                v0x = 0.5f * v0x * (1.0f + erff(v0x * 0.70710678118654752f));
                v0y = 0.5f * v0y * (1.0f + erff(v0y * 0.70710678118654752f));
                v1x = 0.5f * v1x * (1.0f + erff(v1x * 0.70710678118654752f));
                v1y = 0.5f * v1y * (1.0f + erff(v1y * 0.70710678118654752f));
                *reinterpret_cast<float2*>(Cout + (size_t)row0 * NCOLS + col) = make_float2(v0x, v0y);
                *reinterpret_cast<float2*>(Cout + (size_t)row1 * NCOLS + col) = make_float2(v1x, v1y);
            } else if (MODE == 3) {
                float2 r0 = *reinterpret_cast<const float2*>(res + (size_t)row0 * DIMC + col);
                float2 r1 = *reinterpret_cast<const float2*>(res + (size_t)row1 * DIMC + col);
                *reinterpret_cast<float2*>(Cout + (size_t)row0 * NCOLS + col) = make_float2(v0x + r0.x, v0y + r0.y);
                *reinterpret_cast<float2*>(Cout + (size_t)row1 * NCOLS + col) = make_float2(v1x + r1.x, v1y + r1.y);
            } else {
                *reinterpret_cast<float2*>(Cout + (size_t)row0 * NCOLS + col) = make_float2(v0x, v0y);
                *reinterpret_cast<float2*>(Cout + (size_t)row1 * NCOLS + col) = make_float2(v1x, v1y);
            }
        }
    }
}

// ---------------- Tensor-core flash attention -----------------------------
// Block = (window, head, qtile of 128). 8 warps x 16 q rows. Online softmax.
// smem: sQ @0 (16KB), sK @16384 (32KB), sVT @49152 (32KB),
//       sP @81920 (32KB, per-warp 4KB), sV staging overlays sP (33.8KB).
constexpr int SQ_OFF  = 0;
constexpr int SK_OFF  = 16384;
constexpr int SVT_OFF = 49152;
constexpr int SP_OFF  = 81920;
constexpr int ATTN_SMEM = 81920 + 256 * 33 * 4;   // 115712

__global__ void __launch_bounds__(256) attn_tc(
    const float* __restrict__ qkv, const float* __restrict__ biasT,
    const float* __restrict__ mask, float* __restrict__ out)
{
    extern __shared__ char sm[];
    const uint32_t smb = smem_u32(sm);
    const int wi = blockIdx.x, h = blockIdx.y, qt = blockIdx.z;
    const int t = threadIdx.x, lane = t & 31, w = t >> 5;
    const float scale = 0.17677669529663687f;
    const float* base = qkv + (size_t)wi * WTOK * 768;

    // Q tile (128 rows x 32 f32), scaled, swizzled
    #pragma unroll
    for (int i = 0; i < 4; i++) {
        int idx = i * 256 + t;
        int row = idx >> 3, u = idx & 7;
        float4 v = *reinterpret_cast<const float4*>(base + (size_t)(qt * 128 + row) * 768 + h * 32 + u * 4);
        v.x *= scale; v.y *= scale; v.z *= scale; v.w *= scale;
        *reinterpret_cast<float4*>(sm + SQ_OFF + row * 128 + ((u ^ (row & 7)) << 4)) = v;
    }
    // K tile (256 rows x 32)
    #pragma unroll
    for (int i = 0; i < 8; i++) {
        int idx = i * 256 + t;
        int row = idx >> 3, u = idx & 7;
        float4 v = *reinterpret_cast<const float4*>(base + (size_t)row * 768 + 256 + h * 32 + u * 4);
        *reinterpret_cast<float4*>(sm + SK_OFF + row * 128 + ((u ^ (row & 7)) << 4)) = v;
    }
    // V staging (256 rows x 33 f32, padded pitch => conflict-free transpose)
    {
        float* sV = reinterpret_cast<float*>(sm + SP_OFF);
        #pragma unroll
        for (int i = 0; i < 8; i++) {
            int idx = i * 256 + t;
            int row = idx >> 3, u = idx & 7;
            float4 v = *reinterpret_cast<const float4*>(base + (size_t)row * 768 + 512 + h * 32 + u * 4);
            float* d = sV + row * 33 + u * 4;
            d[0] = v.x; d[1] = v.y; d[2] = v.z; d[3] = v.w;
        }
    }
    __syncthreads();
    // transpose: sVT tiles (8 key-chunks of 32) each (32 d-rows x 32 keys), swizzled
    {
        const float* sV = reinterpret_cast<const float*>(sm + SP_OFF);
        const int u = lane >> 2, e = lane & 3;
        #pragma unroll
        for (int d = 0; d < 32; d++) {
            float val = sV[(w * 32 + lane) * 33 + d];
            uint32_t addr = smb + SVT_OFF + w * 4096 + d * 128 + ((u ^ (d & 7)) << 4) + e * 4;
            asm volatile("st.shared.b32 [%0], %1;" :: "r"(addr), "f"(val));
        }
    }
    __syncthreads();

    // Q A-fragments (per warp, fixed)
    const int rlA = lane & 15;
    uint32_t af[4][4];
    #pragma unroll
    for (int ks = 0; ks < 4; ks++) {
        int r = w * 16 + rlA;
        int cch = 2 * ks + (lane >> 4);
        ldsm4(smb + SQ_OFF + r * 128 + ((cch ^ (r & 7)) << 4), af[ks][0], af[ks][1], af[ks][2], af[ks][3]);
    }

    const int g = lane >> 2, tig = lane & 3;
    const int qr = qt * 128 + w * 16 + g;          // window-local q row (row1 = qr+8)
    const float* bT = biasT + (size_t)h * 65536;
    const float* mk = mask + (size_t)wi * 65536;

    float m0v = -1e30f, m1v = -1e30f, l0 = 0.0f, l1 = 0.0f;
    float oacc[4][4];
    #pragma unroll
    for (int dt = 0; dt < 4; dt++)
        #pragma unroll
        for (int r = 0; r < 4; r++) oacc[dt][r] = 0.0f;

    for (int ch = 0; ch < 4; ch++) {
        // ---- S = Q @ K_chunk^T  (16 x 64 per warp) ----
        float sacc[8][4];
        #pragma unroll
        for (int nt = 0; nt < 8; nt++)
            #pragma unroll
            for (int r = 0; r < 4; r++) sacc[nt][r] = 0.0f;

        #pragma unroll
        for (int ks = 0; ks < 4; ks++) {
            #pragma unroll
            for (int nt = 0; nt < 8; nt++) {
                uint32_t b0, b1;
                int r = ch * 64 + nt * 8 + (lane & 7);
                int cch = 2 * ks + ((lane >> 3) & 1);
                ldsm2(smb + SK_OFF + r * 128 + ((cch ^ (r & 7)) << 4), b0, b1);
                mma_tf32(sacc[nt], af[ks][0], af[ks][1], af[ks][2], af[ks][3], b0, b1);
            }
        }

        // ---- bias + mask, rowmax ----
        float mx0 = -1e30f, mx1 = -1e30f;
        #pragma unroll
        for (int nt = 0; nt < 8; nt++) {
            int mc = ch * 64 + nt * 8 + 2 * tig;
            size_t i0 = (size_t)qr * 256 + mc;
            size_t i1 = i0 + 8 * 256;
            float2 bz0 = *reinterpret_cast<const float2*>(bT + i0);
            float2 mk0 = *reinterpret_cast<const float2*>(mk + i0);
            float2 bz1 = *reinterpret_cast<const float2*>(bT + i1);
            float2 mk1 = *reinterpret_cast<const float2*>(mk + i1);
            sacc[nt][0] += bz0.x + mk0.x; sacc[nt][1] += bz0.y + mk0.y;
            sacc[nt][2] += bz1.x + mk1.x; sacc[nt][3] += bz1.y + mk1.y;
            mx0 = fmaxf(mx0, fmaxf(sacc[nt][0], sacc[nt][1]));
            mx1 = fmaxf(mx1, fmaxf(sacc[nt][2], sacc[nt][3]));
        }
        #pragma unroll
        for (int o = 1; o <= 2; o <<= 1) {
            mx0 = fmaxf(mx0, __shfl_xor_sync(0xffffffffu, mx0, o));
            mx1 = fmaxf(mx1, __shfl_xor_sync(0xffffffffu, mx1, o));
        }
        float nm0 = fmaxf(m0v, mx0), nm1 = fmaxf(m1v, mx1);
        float sc0 = __expf(m0v - nm0), sc1 = __expf(m1v - nm1);
        m0v = nm0; m1v = nm1;
        #pragma unroll
        for (int dt = 0; dt < 4; dt++) {
            oacc[dt][0] *= sc0; oacc[dt][1] *= sc0;
            oacc[dt][2] *= sc1; oacc[dt][3] *= sc1;
        }
        float s0 = 0.0f, s1 = 0.0f;
        #pragma unroll
        for (int nt = 0; nt < 8; nt++) {
            sacc[nt][0] = __expf(sacc[nt][0] - nm0);
            sacc[nt][1] = __expf(sacc[nt][1] - nm0);
            sacc[nt][2] = __expf(sacc[nt][2] - nm1);
            sacc[nt][3] = __expf(sacc[nt][3] - nm1);
            s0 += sacc[nt][0] + sacc[nt][1];
            s1 += sacc[nt][2] + sacc[nt][3];
        }
        #pragma unroll
        for (int o = 1; o <= 2; o <<= 1) {
            s0 += __shfl_xor_sync(0xffffffffu, s0, o);
            s1 += __shfl_xor_sync(0xffffffffu, s1, o);
        }
        l0 = l0 * sc0 + s0;
        l1 = l1 * sc1 + s1;

        // ---- store P to per-warp smem (two 16x32 swizzled tiles) ----
        const uint32_t wbase = smb + SP_OFF + w * 4096;
        #pragma unroll
        for (int nt = 0; nt < 8; nt++) {
            int c = nt * 8 + 2 * tig;
            int tt = c >> 5, k2 = c & 31;
            int u = k2 >> 2, e = k2 & 3;
            uint32_t a0 = wbase + tt * 2048 + g * 128 + ((u ^ (g & 7)) << 4) + e * 4;
            asm volatile("st.shared.v2.f32 [%0], {%1,%2};" :: "r"(a0), "f"(sacc[nt][0]), "f"(sacc[nt][1]));
            asm volatile("st.shared.v2.f32 [%0], {%1,%2};" :: "r"(a0 + 8 * 128), "f"(sacc[nt][2]), "f"(sacc[nt][3]));
        }
        __syncwarp();

        // ---- O += P_chunk @ V_chunk ----
        #pragma unroll
        for (int tt = 0; tt < 2; tt++) {
            uint32_t pf[4][4];
            #pragma unroll
            for (int ks = 0; ks < 4; ks++) {
                int cch = 2 * ks + (lane >> 4);
                ldsm4(wbase + tt * 2048 + rlA * 128 + ((cch ^ (rlA & 7)) << 4),
                      pf[ks][0], pf[ks][1], pf[ks][2], pf[ks][3]);
            }
            const uint32_t vtbase = smb + SVT_OFF + (ch * 2 + tt) * 4096;
            #pragma unroll
            for (int ks = 0; ks < 4; ks++) {
                #pragma unroll
                for (int dt = 0; dt < 4; dt++) {
                    uint32_t b0, b1;
                    int r = dt * 8 + (lane & 7);
                    int cch = 2 * ks + ((lane >> 3) & 1);
                    ldsm2(vtbase + r * 128 + ((cch ^ (r & 7)) << 4), b0, b1);
                    mma_tf32(oacc[dt], pf[ks][0], pf[ks][1], pf[ks][2], pf[ks][3], b0, b1);
                }
            }
        }
        __syncwarp();
    }

    // ---- finalize ----
    float inv0 = 1.0f / l0, inv1 = 1.0f / l1;
    int qg = wi * 256 + qr;     // window-ordered token index
    #pragma unroll
    for (int dt = 0; dt < 4; dt++) {
        int col = h * 32 + dt * 8 + 2 * tig;
        *reinterpret_cast<float2*>(out + (size_t)qg * 256 + col) =
            make_float2(oacc[dt][0] * inv0, oacc[dt][1] * inv0);
        *reinterpret_cast<float2*>(out + (size_t)(qg + 8) * 256 + col) =
            make_float2(oacc[dt][2] * inv1, oacc[dt][3] * inv1);
    }
}

// ---------------- launch ----------------
extern "C" void kernel_launch(void* const* d_in, const int* in_sizes, int n_in,
                              void* d_out, int out_size)
{
    const float* x          = (const float*)d_in[0];
    const float* g1         = (const float*)d_in[1];
    const float* b1         = (const float*)d_in[2];
    const float* qkv_w      = (const float*)d_in[3];
    const float* qkv_b      = (const float*)d_in[4];
    const float* bias_table = (const float*)d_in[5];
    const float* proj_w     = (const float*)d_in[6];
    const float* proj_b     = (const float*)d_in[7];
    const float* g2         = (const float*)d_in[8];
    const float* b2         = (const float*)d_in[9];
    const float* fc1_w      = (const float*)d_in[10];
    const float* fc1_b      = (const float*)d_in[11];
    const float* fc2_w      = (const float*)d_in[12];
    const float* fc2_b      = (const float*)d_in[13];
    const float* attn_mask  = (const float*)d_in[14];
    const int*   rel_index  = (const int*)d_in[15];
    float* out = (float*)d_out;

    float *p_ln, *p_qkv, *p_attn, *p_x2, *p_mlp, *p_bias;
    cudaGetSymbolAddress((void**)&p_ln,   g_ln);
    cudaGetSymbolAddress((void**)&p_qkv,  g_qkv);
    cudaGetSymbolAddress((void**)&p_attn, g_attn);
    cudaGetSymbolAddress((void**)&p_x2,   g_x2);
    cudaGetSymbolAddress((void**)&p_mlp,  g_mlp);
    cudaGetSymbolAddress((void**)&p_bias, g_bias);

    const int GEMM_SMEM = 65536;
    cudaFuncSetAttribute((const void*)gemm_mma<256, 768, 0>,  cudaFuncAttributeMaxDynamicSharedMemorySize, GEMM_SMEM);
    cudaFuncSetAttribute((const void*)gemm_mma<256, 256, 1>,  cudaFuncAttributeMaxDynamicSharedMemorySize, GEMM_SMEM);
    cudaFuncSetAttribute((const void*)gemm_mma<256, 1024, 2>, cudaFuncAttributeMaxDynamicSharedMemorySize, GEMM_SMEM);
    cudaFuncSetAttribute((const void*)gemm_mma<1024, 256, 3>, cudaFuncAttributeMaxDynamicSharedMemorySize, GEMM_SMEM);
    cudaFuncSetAttribute(attn_tc, cudaFuncAttributeMaxDynamicSharedMemorySize, ATTN_SMEM);

    biasT_kernel<<<256, 256>>>(bias_table, rel_index, p_bias);
    ln_kernel<<<M_TOK, 256>>>(x, g1, b1, p_ln);
    gemm_mma<256, 768, 0><<<dim3(6, 512), 256, GEMM_SMEM>>>(p_ln, qkv_w, qkv_b, nullptr, p_qkv);
    attn_tc<<<dim3(NWIN, NHEAD, 2), 256, ATTN_SMEM>>>(p_qkv, p_bias, attn_mask, p_attn);
    gemm_mma<256, 256, 1><<<dim3(2, 512), 256, GEMM_SMEM>>>(p_attn, proj_w, proj_b, x, p_x2);
    ln_kernel<<<M_TOK, 256>>>(p_x2, g2, b2, p_ln);
    gemm_mma<256, 1024, 2><<<dim3(8, 512), 256, GEMM_SMEM>>>(p_ln, fc1_w, fc1_b, nullptr, p_mlp);
    gemm_mma<1024, 256, 3><<<dim3(2, 512), 256, GEMM_SMEM>>>(p_mlp, fc2_w, fc2_b, p_x2, out);
}

// round 5
// speedup vs baseline: 4.6163x; 1.1685x over previous
#include <cuda_runtime.h>
#include <cuda_fp16.h>
#include <cstdint>
#include <math.h>

// Problem constants
constexpr int M_TOK  = 65536;
constexpr int DIMC   = 256;
constexpr int NHEAD  = 8;
constexpr int HIDDEN = 1024;
constexpr int NWIN   = 256;
constexpr int WTOK   = 256;

// Scratch
__device__ float  g_ln  [(size_t)M_TOK * DIMC];
__device__ float  g_qkv [(size_t)M_TOK * 3 * DIMC];
__device__ float  g_attn[(size_t)M_TOK * DIMC];
__device__ float  g_x2  [(size_t)M_TOK * DIMC];
__device__ float  g_mlp [(size_t)M_TOK * HIDDEN];
__device__ __half g_bias[(size_t)NHEAD * WTOK * WTOK];   // biasT[h][n][m] (half)

// ---------------- helpers ----------------
__device__ __forceinline__ uint32_t smem_u32(const void* p) {
    uint32_t a;
    asm("{ .reg .u64 t; cvta.to.shared.u64 t, %1; cvt.u32.u64 %0, t; }" : "=r"(a) : "l"(p));
    return a;
}
__device__ __forceinline__ void cp_async16(uint32_t dst, const void* src) {
    asm volatile("cp.async.cg.shared.global [%0], [%1], 16;" :: "r"(dst), "l"(src));
}
#define CP_COMMIT() asm volatile("cp.async.commit_group;")
#define CP_WAIT(n)  asm volatile("cp.async.wait_group %0;" :: "n"(n))
__device__ __forceinline__ void ldsm4(uint32_t addr, uint32_t& r0, uint32_t& r1, uint32_t& r2, uint32_t& r3) {
    asm volatile("ldmatrix.sync.aligned.m8n8.x4.shared.b16 {%0,%1,%2,%3}, [%4];"
                 : "=r"(r0), "=r"(r1), "=r"(r2), "=r"(r3) : "r"(addr));
}
__device__ __forceinline__ void ldsm2(uint32_t addr, uint32_t& r0, uint32_t& r1) {
    asm volatile("ldmatrix.sync.aligned.m8n8.x2.shared.b16 {%0,%1}, [%2];"
                 : "=r"(r0), "=r"(r1) : "r"(addr));
}
__device__ __forceinline__ void mma_tf32(float c[4], uint32_t a0, uint32_t a1, uint32_t a2, uint32_t a3,
                                         uint32_t b0, uint32_t b1) {
    asm volatile("mma.sync.aligned.m16n8k8.row.col.f32.tf32.tf32.f32 "
                 "{%0,%1,%2,%3}, {%4,%5,%6,%7}, {%8,%9}, {%0,%1,%2,%3};"
                 : "+f"(c[0]), "+f"(c[1]), "+f"(c[2]), "+f"(c[3])
                 : "r"(a0), "r"(a1), "r"(a2), "r"(a3), "r"(b0), "r"(b1));
}
__device__ __forceinline__ void mma_f16(float c[4], uint32_t a0, uint32_t a1, uint32_t a2, uint32_t a3,
                                        uint32_t b0, uint32_t b1) {
    asm volatile("mma.sync.aligned.m16n8k16.row.col.f32.f16.f16.f32 "
                 "{%0,%1,%2,%3}, {%4,%5,%6,%7}, {%8,%9}, {%0,%1,%2,%3};"
                 : "+f"(c[0]), "+f"(c[1]), "+f"(c[2]), "+f"(c[3])
                 : "r"(a0), "r"(a1), "r"(a2), "r"(a3), "r"(b0), "r"(b1));
}
__device__ __forceinline__ uint32_t pkh2(float a, float b) {
    __half2 h = __floats2half2_rn(a, b);
    return *reinterpret_cast<uint32_t*>(&h);
}

// roll(-2)+window-partition row map (bijection; also the output scatter)
__device__ __forceinline__ int src_index(int r) {
    int wi = r >> 8, pos = r & 255;
    int h1 = (wi >> 6) & 3, w1 = (wi >> 4) & 3, h2 = (wi >> 2) & 3, w2 = wi & 3;
    int a  = (pos >> 6) & 3, b  = (pos >> 4) & 3, c  = (pos >> 2) & 3, d  = pos & 3;
    int A_ = (h1 * 4 + a + 2) & 15;
    int B_ = (w1 * 4 + b + 2) & 15;
    int C_ = (h2 * 4 + c + 2) & 15;
    int D_ = (w2 * 4 + d + 2) & 15;
    return ((A_ * 16 + B_) * 16 + C_) * 16 + D_;
}
// shifted-window mask region id (slice classes of UNROLLED window coordinate)
__device__ __forceinline__ int cls3(int c) { return (c < 12) ? 0 : ((c < 14) ? 1 : 2); }
__device__ __forceinline__ int region_id(int wi, int pos) {
    int cA = cls3(((wi >> 6) & 3) * 4 + ((pos >> 6) & 3));
    int cB = cls3(((wi >> 4) & 3) * 4 + ((pos >> 4) & 3));
    int cC = cls3(((wi >> 2) & 3) * 4 + ((pos >> 2) & 3));
    int cD = cls3((wi & 3) * 4 + (pos & 3));
    return ((cA * 3 + cB) * 3 + cC) * 3 + cD;
}

// ---------------- LayerNorm ----------------
__global__ void __launch_bounds__(256) ln_kernel(
    const float* __restrict__ x, const float* __restrict__ g,
    const float* __restrict__ b, float* __restrict__ out)
{
    int row = blockIdx.x, t = threadIdx.x;
    float v = x[(size_t)row * DIMC + t];
    __shared__ float red[8];
    float s = v;
    #pragma unroll
    for (int o = 16; o; o >>= 1) s += __shfl_xor_sync(0xffffffffu, s, o);
    if ((t & 31) == 0) red[t >> 5] = s;
    __syncthreads();
    float tot = red[0]+red[1]+red[2]+red[3]+red[4]+red[5]+red[6]+red[7];
    float mu = tot * (1.0f / DIMC);
    __syncthreads();
    float dv = v - mu;
    s = dv * dv;
    #pragma unroll
    for (int o = 16; o; o >>= 1) s += __shfl_xor_sync(0xffffffffu, s, o);
    if ((t & 31) == 0) red[t >> 5] = s;
    __syncthreads();
    tot = red[0]+red[1]+red[2]+red[3]+red[4]+red[5]+red[6]+red[7];
    float rstd = rsqrtf(tot * (1.0f / DIMC) + 1e-5f);
    out[(size_t)row * DIMC + t] = dv * rstd * g[t] + b[t];
}

// ---------------- biasT gather (half): biasT[h][n][m] = table[rel[n,m]][h] -
__global__ void __launch_bounds__(256) biasT_kernel(
    const float* __restrict__ table, const int* __restrict__ rel, __half* __restrict__ biasT)
{
    int nm = blockIdx.x * 256 + threadIdx.x;
    int ri = rel[nm];
    #pragma unroll
    for (int h = 0; h < 8; h++)
        biasT[(size_t)h * 65536 + nm] = __float2half(table[ri * 8 + h]);
}

// ---------------- tf32 mma.sync GEMM with cp.async double buffer ----------
template<int KDIM, int NCOLS, int MODE>
__global__ void __launch_bounds__(256, 2) gemm_mma(
    const float* __restrict__ A, const float* __restrict__ Bw,
    const float* __restrict__ bias, const float* __restrict__ res,
    float* __restrict__ Cout)
{
    extern __shared__ char sm[];
    const uint32_t smb = smem_u32(sm);
    const int t = threadIdx.x, lane = t & 31, warp = t >> 5;
    const int wm = warp & 1, wn = warp >> 1;
    const int m0 = blockIdx.y * 128, n0 = blockIdx.x * 128;
    constexpr int NC = KDIM / 32;

    const float* aptr[4];
    const float* bptr[4];
    uint32_t sA[4], sB[4];
    #pragma unroll
    for (int i = 0; i < 4; i++) {
        int idx = i * 256 + t;
        int row = idx >> 3, u = idx & 7;
        int gr = (MODE == 0) ? src_index(m0 + row) : (m0 + row);
        aptr[i] = A  + (size_t)gr * KDIM + u * 4;
        bptr[i] = Bw + (size_t)(n0 + row) * KDIM + u * 4;
        uint32_t off = row * 128 + ((u ^ (row & 7)) << 4);
        sA[i] = smb + off;
        sB[i] = smb + 32768 + off;
    }

    #pragma unroll
    for (int i = 0; i < 4; i++) {
        cp_async16(sA[i], aptr[i]);
        cp_async16(sB[i], bptr[i]);
    }
    CP_COMMIT();

    float acc[4][4][4];
    #pragma unroll
    for (int ms = 0; ms < 4; ms++)
        #pragma unroll
        for (int ns = 0; ns < 4; ns++)
            #pragma unroll
            for (int r = 0; r < 4; r++) acc[ms][ns][r] = 0.0f;

    for (int ch = 0; ch < NC; ch++) {
        const uint32_t bofs = (ch & 1) * 16384;
        if (ch + 1 < NC) {
            const uint32_t nofs = ((ch + 1) & 1) * 16384;
            #pragma unroll
            for (int i = 0; i < 4; i++) {
                cp_async16(sA[i] + nofs, aptr[i] + (ch + 1) * 32);
                cp_async16(sB[i] + nofs, bptr[i] + (ch + 1) * 32);
            }
            CP_COMMIT();
            CP_WAIT(1);
        } else {
            CP_WAIT(0);
        }
        __syncthreads();

        const uint32_t abase = smb + bofs;
        const uint32_t bbase = smb + 32768 + bofs;
        const int rlA = lane & 15;
        #pragma unroll
        for (int ks = 0; ks < 4; ks++) {
            uint32_t af[4][4];
            #pragma unroll
            for (int ms = 0; ms < 4; ms++) {
                int r = wm * 64 + ms * 16 + rlA;
                int cch = 2 * ks + (lane >> 4);
                ldsm4(abase + r * 128 + ((cch ^ (r & 7)) << 4), af[ms][0], af[ms][1], af[ms][2], af[ms][3]);
            }
            uint32_t bf[4][2];
            #pragma unroll
            for (int ns = 0; ns < 4; ns++) {
                int r = wn * 32 + ns * 8 + (lane & 7);
                int cch = 2 * ks + ((lane >> 3) & 1);
                ldsm2(bbase + r * 128 + ((cch ^ (r & 7)) << 4), bf[ns][0], bf[ns][1]);
            }
            #pragma unroll
            for (int ms = 0; ms < 4; ms++)
                #pragma unroll
                for (int ns = 0; ns < 4; ns++)
                    mma_tf32(acc[ms][ns], af[ms][0], af[ms][1], af[ms][2], af[ms][3], bf[ns][0], bf[ns][1]);
        }
        __syncthreads();
    }

    const int g = lane >> 2, tig = lane & 3;
    #pragma unroll
    for (int ms = 0; ms < 4; ms++) {
        int row0 = m0 + wm * 64 + ms * 16 + g;
        int row1 = row0 + 8;
        int or0 = (MODE == 1) ? src_index(row0) : row0;
        int or1 = (MODE == 1) ? src_index(row1) : row1;
        #pragma unroll
        for (int ns = 0; ns < 4; ns++) {
            int col = n0 + wn * 32 + ns * 8 + 2 * tig;
            float bx = bias[col], by = bias[col + 1];
            float v0x = acc[ms][ns][0] + bx, v0y = acc[ms][ns][1] + by;
            float v1x = acc[ms][ns][2] + bx, v1y = acc[ms][ns][3] + by;
            if (MODE == 1) {
                float2 r0 = *reinterpret_cast<const float2*>(res + (size_t)or0 * DIMC + col);
                float2 r1 = *reinterpret_cast<const float2*>(res + (size_t)or1 * DIMC + col);
                *reinterpret_cast<float2*>(Cout + (size_t)or0 * DIMC + col) = make_float2(v0x + r0.x, v0y + r0.y);
                *reinterpret_cast<float2*>(Cout + (size_t)or1 * DIMC + col) = make_float2(v1x + r1.x, v1y + r1.y);
            } else if (MODE == 2) {
                v0x = 0.5f * v0x * (1.0f + erff(v0x * 0.70710678118654752f));
                v0y = 0.5f * v0y * (1.0f + erff(v0y * 0.70710678118654752f));
                v1x = 0.5f * v1x * (1.0f + erff(v1x * 0.70710678118654752f));
                v1y = 0.5f * v1y * (1.0f + erff(v1y * 0.70710678118654752f));
                *reinterpret_cast<float2*>(Cout + (size_t)row0 * NCOLS + col) = make_float2(v0x, v0y);
                *reinterpret_cast<float2*>(Cout + (size_t)row1 * NCOLS + col) = make_float2(v1x, v1y);
            } else if (MODE == 3) {
                float2 r0 = *reinterpret_cast<const float2*>(res + (size_t)row0 * DIMC + col);
                float2 r1 = *reinterpret_cast<const float2*>(res + (size_t)row1 * DIMC + col);
                *reinterpret_cast<float2*>(Cout + (size_t)row0 * NCOLS + col) = make_float2(v0x + r0.x, v0y + r0.y);
                *reinterpret_cast<float2*>(Cout + (size_t)row1 * NCOLS + col) = make_float2(v1x + r1.x, v1y + r1.y);
            } else {
                *reinterpret_cast<float2*>(Cout + (size_t)row0 * NCOLS + col) = make_float2(v0x, v0y);
                *reinterpret_cast<float2*>(Cout + (size_t)row1 * NCOLS + col) = make_float2(v1x, v1y);
            }
        }
    }
}

// ---------------- fp16 tensor-core flash attention -------------------------
// Block = (window, head, qtile of 128). 8 warps x 16 q rows. Online softmax.
// smem (bytes): Q half @0 (8K, pitch 64), K half @8192 (16K, pitch 64),
// VT half @24576 (16K, 32 d-rows x 256 keys, pitch 512),
// P half @40960 (16K, per-warp 2K, pitch 128),
// V f32 staging @40960 overlays P (33792), sid @74752 (1K). Total 75776.
constexpr int Q_OFF   = 0;
constexpr int K_OFF   = 8192;
constexpr int VT_OFF  = 24576;
constexpr int P_OFF   = 40960;
constexpr int STG_OFF = 40960;
constexpr int SID_OFF = 74752;
constexpr int ATTN_SMEM = 75776;

__global__ void __launch_bounds__(256, 2) attn_tc(
    const float* __restrict__ qkv, const __half* __restrict__ biasT,
    float* __restrict__ out)
{
    extern __shared__ char sm[];
    const uint32_t smb = smem_u32(sm);
    const int wi = blockIdx.x, h = blockIdx.y, qt = blockIdx.z;
    const int t = threadIdx.x, lane = t & 31, w = t >> 5;
    const float scale = 0.17677669529663687f;
    const float* base = qkv + (size_t)wi * WTOK * 768;
    int* sid = reinterpret_cast<int*>(sm + SID_OFF);

    // region ids for mask (once per block)
    sid[t] = region_id(wi, t);

    // Q tile: 128 rows x 32 half (scaled). 256 units = 128 rows x 2 segs.
    {
        int row = t >> 1, seg = t & 1;
        const float* src = base + (size_t)(qt * 128 + row) * 768 + h * 32 + seg * 16;
        float4 v0 = *reinterpret_cast<const float4*>(src);
        float4 v1 = *reinterpret_cast<const float4*>(src + 4);
        float4 v2 = *reinterpret_cast<const float4*>(src + 8);
        float4 v3 = *reinterpret_cast<const float4*>(src + 12);
        uint32_t p0 = pkh2(v0.x*scale, v0.y*scale), p1 = pkh2(v0.z*scale, v0.w*scale);
        uint32_t p2 = pkh2(v1.x*scale, v1.y*scale), p3 = pkh2(v1.z*scale, v1.w*scale);
        uint32_t p4 = pkh2(v2.x*scale, v2.y*scale), p5 = pkh2(v2.z*scale, v2.w*scale);
        uint32_t p6 = pkh2(v3.x*scale, v3.y*scale), p7 = pkh2(v3.z*scale, v3.w*scale);
        int sw = (row >> 1) & 3;
        uint32_t a0 = smb + Q_OFF + row * 64 + (((seg*2)   ^ sw) << 4);
        uint32_t a1 = smb + Q_OFF + row * 64 + (((seg*2+1) ^ sw) << 4);
        asm volatile("st.shared.v4.b32 [%0], {%1,%2,%3,%4};" :: "r"(a0), "r"(p0), "r"(p1), "r"(p2), "r"(p3));
        asm volatile("st.shared.v4.b32 [%0], {%1,%2,%3,%4};" :: "r"(a1), "r"(p4), "r"(p5), "r"(p6), "r"(p7));
    }
    // K tile: 256 rows x 32 half. 512 units.
    #pragma unroll
    for (int i = 0; i < 2; i++) {
        int idx = i * 256 + t;
        int row = idx >> 1, seg = idx & 1;
        const float* src = base + (size_t)row * 768 + 256 + h * 32 + seg * 16;
        float4 v0 = *reinterpret_cast<const float4*>(src);
        float4 v1 = *reinterpret_cast<const float4*>(src + 4);
        float4 v2 = *reinterpret_cast<const float4*>(src + 8);
        float4 v3 = *reinterpret_cast<const float4*>(src + 12);
        uint32_t p0 = pkh2(v0.x, v0.y), p1 = pkh2(v0.z, v0.w);
        uint32_t p2 = pkh2(v1.x, v1.y), p3 = pkh2(v1.z, v1.w);
        uint32_t p4 = pkh2(v2.x, v2.y), p5 = pkh2(v2.z, v2.w);
        uint32_t p6 = pkh2(v3.x, v3.y), p7 = pkh2(v3.z, v3.w);
        int sw = (row >> 1) & 3;
        uint32_t a0 = smb + K_OFF + row * 64 + (((seg*2)   ^ sw) << 4);
        uint32_t a1 = smb + K_OFF + row * 64 + (((seg*2+1) ^ sw) << 4);
        asm volatile("st.shared.v4.b32 [%0], {%1,%2,%3,%4};" :: "r"(a0), "r"(p0), "r"(p1), "r"(p2), "r"(p3));
        asm volatile("st.shared.v4.b32 [%0], {%1,%2,%3,%4};" :: "r"(a1), "r"(p4), "r"(p5), "r"(p6), "r"(p7));
    }
    // V staging (f32, 256 rows x 33 pitch)
    {
        float* sV = reinterpret_cast<float*>(sm + STG_OFF);
        #pragma unroll
        for (int i = 0; i < 8; i++) {
            int idx = i * 256 + t;
            int row = idx >> 3, u = idx & 7;
            float4 v = *reinterpret_cast<const float4*>(base + (size_t)row * 768 + 512 + h * 32 + u * 4);
            float* d = sV + row * 33 + u * 4;
            d[0] = v.x; d[1] = v.y; d[2] = v.z; d[3] = v.w;
        }
    }
    __syncthreads();
    // transpose V -> VT (half): rows d (32), cols keys (256), pitch 512B
    if (t < 128) {
        const float* sV = reinterpret_cast<const float*>(sm + STG_OFF);
        int p = t;                         // key pair: keys 2p, 2p+1
        #pragma unroll
        for (int d = 0; d < 32; d++) {
            uint32_t h2 = pkh2(sV[(2*p) * 33 + d], sV[(2*p+1) * 33 + d]);
            uint32_t addr = smb + VT_OFF + d * 512 + ((((uint32_t)(p >> 2)) ^ (d & 7)) << 4) + (p & 3) * 4;
            asm volatile("st.shared.b32 [%0], %1;" :: "r"(addr), "r"(h2));
        }
    }
    __syncthreads();

    // Q A-fragments (fixed per warp): m16 x k32 = 2 ksteps of k16
    const int rlA = lane & 15;
    uint32_t af[2][4];
    #pragma unroll
    for (int ks = 0; ks < 2; ks++) {
        int r = w * 16 + rlA;
        int u = 2 * ks + (lane >> 4);
        ldsm4(smb + Q_OFF + r * 64 + ((u ^ ((r >> 1) & 3)) << 4), af[ks][0], af[ks][1], af[ks][2], af[ks][3]);
    }

    const int g = lane >> 2, tig = lane & 3;
    const int qr = qt * 128 + w * 16 + g;          // window-local q row (row1 = qr+8)
    const __half* bT = biasT + (size_t)h * 65536;
    const int idq0 = sid[qr], idq1 = sid[qr + 8];

    float m0v = -1e30f, m1v = -1e30f, l0 = 0.0f, l1 = 0.0f;
    float oacc[4][4];
    #pragma unroll
    for (int dt = 0; dt < 4; dt++)
        #pragma unroll
        for (int r = 0; r < 4; r++) oacc[dt][r] = 0.0f;

    for (int ch = 0; ch < 4; ch++) {
        // ---- S = Q @ K_chunk^T (16 x 64 per warp) ----
        float sacc[8][4];
        #pragma unroll
        for (int nt = 0; nt < 8; nt++)
            #pragma unroll
            for (int r = 0; r < 4; r++) sacc[nt][r] = 0.0f;

        #pragma unroll
        for (int ks = 0; ks < 2; ks++) {
            #pragma unroll
            for (int nt = 0; nt < 8; nt++) {
                uint32_t b0, b1;
                int r = ch * 64 + nt * 8 + (lane & 7);
                int u = 2 * ks + ((lane >> 3) & 1);
                ldsm2(smb + K_OFF + r * 64 + ((u ^ ((r >> 1) & 3)) << 4), b0, b1);
                mma_f16(sacc[nt], af[ks][0], af[ks][1], af[ks][2], af[ks][3], b0, b1);
            }
        }

        // ---- bias + analytic mask, rowmax ----
        float mx0 = -1e30f, mx1 = -1e30f;
        #pragma unroll
        for (int nt = 0; nt < 8; nt++) {
            int mc = ch * 64 + nt * 8 + 2 * tig;
            int2 ids = *reinterpret_cast<const int2*>(sid + mc);
            float mk00 = (idq0 == ids.x) ? 0.0f : -100.0f;
            float mk01 = (idq0 == ids.y) ? 0.0f : -100.0f;
            float mk10 = (idq1 == ids.x) ? 0.0f : -100.0f;
            float mk11 = (idq1 == ids.y) ? 0.0f : -100.0f;
            size_t i0 = (size_t)qr * 256 + mc;
            size_t i1 = i0 + 8 * 256;
            float2 b0 = __half22float2(*reinterpret_cast<const __half2*>(bT + i0));
            float2 b1 = __half22float2(*reinterpret_cast<const __half2*>(bT + i1));
            sacc[nt][0] += b0.x + mk00; sacc[nt][1] += b0.y + mk01;
            sacc[nt][2] += b1.x + mk10; sacc[nt][3] += b1.y + mk11;
            mx0 = fmaxf(mx0, fmaxf(sacc[nt][0], sacc[nt][1]));
            mx1 = fmaxf(mx1, fmaxf(sacc[nt][2], sacc[nt][3]));
        }
        #pragma unroll
        for (int o = 1; o <= 2; o <<= 1) {
            mx0 = fmaxf(mx0, __shfl_xor_sync(0xffffffffu, mx0, o));
            mx1 = fmaxf(mx1, __shfl_xor_sync(0xffffffffu, mx1, o));
        }
        float nm0 = fmaxf(m0v, mx0), nm1 = fmaxf(m1v, mx1);
        float sc0 = __expf(m0v - nm0), sc1 = __expf(m1v - nm1);
        m0v = nm0; m1v = nm1;
        #pragma unroll
        for (int dt = 0; dt < 4; dt++) {
            oacc[dt][0] *= sc0; oacc[dt][1] *= sc0;
            oacc[dt][2] *= sc1; oacc[dt][3] *= sc1;
        }
        float s0 = 0.0f, s1 = 0.0f;
        #pragma unroll
        for (int nt = 0; nt < 8; nt++) {
            sacc[nt][0] = __expf(sacc[nt][0] - nm0);
            sacc[nt][1] = __expf(sacc[nt][1] - nm0);
            sacc[nt][2] = __expf(sacc[nt][2] - nm1);
            sacc[nt][3] = __expf(sacc[nt][3] - nm1);
            s0 += sacc[nt][0] + sacc[nt][1];
            s1 += sacc[nt][2] + sacc[nt][3];
        }
        #pragma unroll
        for (int o = 1; o <= 2; o <<= 1) {
            s0 += __shfl_xor_sync(0xffffffffu, s0, o);
            s1 += __shfl_xor_sync(0xffffffffu, s1, o);
        }
        l0 = l0 * sc0 + s0;
        l1 = l1 * sc1 + s1;

        // ---- store P (half) to per-warp smem: 16 rows x 64 halves, pitch 128 ----
        const uint32_t wbase = smb + P_OFF + w * 2048;
        #pragma unroll
        for (int nt = 0; nt < 8; nt++) {
            uint32_t h01 = pkh2(sacc[nt][0], sacc[nt][1]);
            uint32_t h23 = pkh2(sacc[nt][2], sacc[nt][3]);
            uint32_t a0 = wbase + g * 128 + ((nt ^ (g & 7)) << 4) + tig * 4;
            asm volatile("st.shared.b32 [%0], %1;" :: "r"(a0), "r"(h01));
            asm volatile("st.shared.b32 [%0], %1;" :: "r"(a0 + 8 * 128), "r"(h23));
        }
        __syncwarp();

        // ---- O += P_chunk @ V_chunk (k = 64 keys = 4 ksteps of 16) ----
        #pragma unroll
        for (int ks = 0; ks < 4; ks++) {
            uint32_t pf[4];
            {
                int u = 2 * ks + (lane >> 4);
                ldsm4(wbase + rlA * 128 + ((u ^ (rlA & 7)) << 4), pf[0], pf[1], pf[2], pf[3]);
            }
            #pragma unroll
            for (int dt = 0; dt < 4; dt++) {
                uint32_t b0, b1;
                int r = dt * 8 + (lane & 7);
                int u = ch * 8 + ks * 2 + ((lane >> 3) & 1);
                ldsm2(smb + VT_OFF + r * 512 + ((u ^ (r & 7)) << 4), b0, b1);
                mma_f16(oacc[dt], pf[0], pf[1], pf[2], pf[3], b0, b1);
            }
        }
        __syncwarp();
    }

    // ---- finalize ----
    float inv0 = 1.0f / l0, inv1 = 1.0f / l1;
    int qg = wi * 256 + qr;
    #pragma unroll
    for (int dt = 0; dt < 4; dt++) {
        int col = h * 32 + dt * 8 + 2 * tig;
        *reinterpret_cast<float2*>(out + (size_t)qg * 256 + col) =
            make_float2(oacc[dt][0] * inv0, oacc[dt][1] * inv0);
        *reinterpret_cast<float2*>(out + (size_t)(qg + 8) * 256 + col) =
            make_float2(oacc[dt][2] * inv1, oacc[dt][3] * inv1);
    }
}

// ---------------- launch ----------------
extern "C" void kernel_launch(void* const* d_in, const int* in_sizes, int n_in,
                              void* d_out, int out_size)
{
    const float* x          = (const float*)d_in[0];
    const float* g1         = (const float*)d_in[1];
    const float* b1         = (const float*)d_in[2];
    const float* qkv_w      = (const float*)d_in[3];
    const float* qkv_b      = (const float*)d_in[4];
    const float* bias_table = (const float*)d_in[5];
    const float* proj_w     = (const float*)d_in[6];
    const float* proj_b     = (const float*)d_in[7];
    const float* g2         = (const float*)d_in[8];
    const float* b2         = (const float*)d_in[9];
    const float* fc1_w      = (const float*)d_in[10];
    const float* fc1_b      = (const float*)d_in[11];
    const float* fc2_w      = (const float*)d_in[12];
    const float* fc2_b      = (const float*)d_in[13];
    const int*   rel_index  = (const int*)d_in[15];
    float* out = (float*)d_out;

    float *p_ln, *p_qkv, *p_attn, *p_x2, *p_mlp;
    __half* p_bias;
    cudaGetSymbolAddress((void**)&p_ln,   g_ln);
    cudaGetSymbolAddress((void**)&p_qkv,  g_qkv);
    cudaGetSymbolAddress((void**)&p_attn, g_attn);
    cudaGetSymbolAddress((void**)&p_x2,   g_x2);
    cudaGetSymbolAddress((void**)&p_mlp,  g_mlp);
    cudaGetSymbolAddress((void**)&p_bias, g_bias);

    const int GEMM_SMEM = 65536;
    cudaFuncSetAttribute((const void*)gemm_mma<256, 768, 0>,  cudaFuncAttributeMaxDynamicSharedMemorySize, GEMM_SMEM);
    cudaFuncSetAttribute((const void*)gemm_mma<256, 256, 1>,  cudaFuncAttributeMaxDynamicSharedMemorySize, GEMM_SMEM);
    cudaFuncSetAttribute((const void*)gemm_mma<256, 1024, 2>, cudaFuncAttributeMaxDynamicSharedMemorySize, GEMM_SMEM);
    cudaFuncSetAttribute((const void*)gemm_mma<1024, 256, 3>, cudaFuncAttributeMaxDynamicSharedMemorySize, GEMM_SMEM);
    cudaFuncSetAttribute(attn_tc, cudaFuncAttributeMaxDynamicSharedMemorySize, ATTN_SMEM);

    biasT_kernel<<<256, 256>>>(bias_table, rel_index, p_bias);
    ln_kernel<<<M_TOK, 256>>>(x, g1, b1, p_ln);
    gemm_mma<256, 768, 0><<<dim3(6, 512), 256, GEMM_SMEM>>>(p_ln, qkv_w, qkv_b, nullptr, p_qkv);
    attn_tc<<<dim3(NWIN, NHEAD, 2), 256, ATTN_SMEM>>>(p_qkv, p_bias, p_attn);
    gemm_mma<256, 256, 1><<<dim3(2, 512), 256, GEMM_SMEM>>>(p_attn, proj_w, proj_b, x, p_x2);
    ln_kernel<<<M_TOK, 256>>>(p_x2, g2, b2, p_ln);
    gemm_mma<256, 1024, 2><<<dim3(8, 512), 256, GEMM_SMEM>>>(p_ln, fc1_w, fc1_b, nullptr, p_mlp);
    gemm_mma<1024, 256, 3><<<dim3(2, 512), 256, GEMM_SMEM>>>(p_mlp, fc2_w, fc2_b, p_x2, out);
}

// round 6
// speedup vs baseline: 6.1772x; 1.3381x over previous
#include <cuda_runtime.h>
#include <cuda_fp16.h>
#include <cstdint>
#include <math.h>

// Problem constants
constexpr int M_TOK  = 65536;
constexpr int DIMC   = 256;
constexpr int NHEAD  = 8;
constexpr int HIDDEN = 1024;
constexpr int NWIN   = 256;
constexpr int WTOK   = 256;

// Scratch (half activation pipeline)
__device__ __half g_lnh [(size_t)M_TOK * DIMC];
__device__ __half g_qkvh[(size_t)M_TOK * 3 * DIMC];
__device__ __half g_attnh[(size_t)M_TOK * DIMC];
__device__ __half g_mlph[(size_t)M_TOK * HIDDEN];
__device__ float  g_x2  [(size_t)M_TOK * DIMC];
__device__ __half g_bias[(size_t)NHEAD * WTOK * WTOK];   // biasT[h][n][m]
// half weights
__device__ __half g_wq[768 * 256];
__device__ __half g_wp[256 * 256];
__device__ __half g_w1[1024 * 256];
__device__ __half g_w2[256 * 1024];

// ---------------- helpers ----------------
__device__ __forceinline__ uint32_t smem_u32(const void* p) {
    uint32_t a;
    asm("{ .reg .u64 t; cvta.to.shared.u64 t, %1; cvt.u32.u64 %0, t; }" : "=r"(a) : "l"(p));
    return a;
}
__device__ __forceinline__ void cp_async16(uint32_t dst, const void* src) {
    asm volatile("cp.async.cg.shared.global [%0], [%1], 16;" :: "r"(dst), "l"(src));
}
#define CP_COMMIT() asm volatile("cp.async.commit_group;")
#define CP_WAIT(n)  asm volatile("cp.async.wait_group %0;" :: "n"(n))
__device__ __forceinline__ void ldsm4(uint32_t addr, uint32_t& r0, uint32_t& r1, uint32_t& r2, uint32_t& r3) {
    asm volatile("ldmatrix.sync.aligned.m8n8.x4.shared.b16 {%0,%1,%2,%3}, [%4];"
                 : "=r"(r0), "=r"(r1), "=r"(r2), "=r"(r3) : "r"(addr));
}
__device__ __forceinline__ void ldsm2(uint32_t addr, uint32_t& r0, uint32_t& r1) {
    asm volatile("ldmatrix.sync.aligned.m8n8.x2.shared.b16 {%0,%1}, [%2];"
                 : "=r"(r0), "=r"(r1) : "r"(addr));
}
__device__ __forceinline__ void ldsm2t(uint32_t addr, uint32_t& r0, uint32_t& r1) {
    asm volatile("ldmatrix.sync.aligned.m8n8.x2.trans.shared.b16 {%0,%1}, [%2];"
                 : "=r"(r0), "=r"(r1) : "r"(addr));
}
__device__ __forceinline__ void mma_f16(float c[4], uint32_t a0, uint32_t a1, uint32_t a2, uint32_t a3,
                                        uint32_t b0, uint32_t b1) {
    asm volatile("mma.sync.aligned.m16n8k16.row.col.f32.f16.f16.f32 "
                 "{%0,%1,%2,%3}, {%4,%5,%6,%7}, {%8,%9}, {%0,%1,%2,%3};"
                 : "+f"(c[0]), "+f"(c[1]), "+f"(c[2]), "+f"(c[3])
                 : "r"(a0), "r"(a1), "r"(a2), "r"(a3), "r"(b0), "r"(b1));
}
__device__ __forceinline__ uint32_t pkh2(float a, float b) {
    __half2 h = __floats2half2_rn(a, b);
    return *reinterpret_cast<uint32_t*>(&h);
}

// roll(-2)+window-partition row map (bijection; also the output scatter)
__device__ __forceinline__ int src_index(int r) {
    int wi = r >> 8, pos = r & 255;
    int h1 = (wi >> 6) & 3, w1 = (wi >> 4) & 3, h2 = (wi >> 2) & 3, w2 = wi & 3;
    int a  = (pos >> 6) & 3, b  = (pos >> 4) & 3, c  = (pos >> 2) & 3, d  = pos & 3;
    int A_ = (h1 * 4 + a + 2) & 15;
    int B_ = (w1 * 4 + b + 2) & 15;
    int C_ = (h2 * 4 + c + 2) & 15;
    int D_ = (w2 * 4 + d + 2) & 15;
    return ((A_ * 16 + B_) * 16 + C_) * 16 + D_;
}
// shifted-window mask region id
__device__ __forceinline__ int cls3(int c) { return (c < 12) ? 0 : ((c < 14) ? 1 : 2); }
__device__ __forceinline__ int region_id(int wi, int pos) {
    int cA = cls3(((wi >> 6) & 3) * 4 + ((pos >> 6) & 3));
    int cB = cls3(((wi >> 4) & 3) * 4 + ((pos >> 4) & 3));
    int cC = cls3(((wi >> 2) & 3) * 4 + ((pos >> 2) & 3));
    int cD = cls3((wi & 3) * 4 + (pos & 3));
    return ((cA * 3 + cB) * 3 + cC) * 3 + cD;
}

// ---------------- fp32 -> fp16 convert ----------------
__global__ void __launch_bounds__(256) f2h_kernel(const float* __restrict__ s, __half* __restrict__ d, int n) {
    int i = (blockIdx.x * 256 + threadIdx.x) * 4;
    if (i < n) {
        float4 v = *reinterpret_cast<const float4*>(s + i);
        uint2 o;
        o.x = pkh2(v.x, v.y);
        o.y = pkh2(v.z, v.w);
        *reinterpret_cast<uint2*>(d + i) = o;
    }
}

// ---------------- LayerNorm (fp32 in -> half out) ----------------
__global__ void __launch_bounds__(256) ln_kernel(
    const float* __restrict__ x, const float* __restrict__ g,
    const float* __restrict__ b, __half* __restrict__ out)
{
    int row = blockIdx.x, t = threadIdx.x;
    float v = x[(size_t)row * DIMC + t];
    __shared__ float red[8];
    float s = v;
    #pragma unroll
    for (int o = 16; o; o >>= 1) s += __shfl_xor_sync(0xffffffffu, s, o);
    if ((t & 31) == 0) red[t >> 5] = s;
    __syncthreads();
    float tot = red[0]+red[1]+red[2]+red[3]+red[4]+red[5]+red[6]+red[7];
    float mu = tot * (1.0f / DIMC);
    __syncthreads();
    float dv = v - mu;
    s = dv * dv;
    #pragma unroll
    for (int o = 16; o; o >>= 1) s += __shfl_xor_sync(0xffffffffu, s, o);
    if ((t & 31) == 0) red[t >> 5] = s;
    __syncthreads();
    tot = red[0]+red[1]+red[2]+red[3]+red[4]+red[5]+red[6]+red[7];
    float rstd = rsqrtf(tot * (1.0f / DIMC) + 1e-5f);
    out[(size_t)row * DIMC + t] = __float2half(dv * rstd * g[t] + b[t]);
}

// ---------------- biasT gather ----------------
__global__ void __launch_bounds__(256) biasT_kernel(
    const float* __restrict__ table, const int* __restrict__ rel, __half* __restrict__ biasT)
{
    int nm = blockIdx.x * 256 + threadIdx.x;
    int ri = rel[nm];
    #pragma unroll
    for (int h = 0; h < 8; h++)
        biasT[(size_t)h * 65536 + nm] = __float2half(table[ri * 8 + h]);
}

// swizzled smem offset: 64B-pitch rows, 4x16B units
#define SW64(r, u) ((r) * 64 + (((u) ^ (((r) >> 1) & 3)) << 4))

// ---------------- fp16 mma GEMM: C = A @ Bw^T (+bias, epilogue) ------------
// MODE 0: QKV (gather A rows, q-scale, half out)  MODE 1: proj (scatter+res, f32 out)
// MODE 2: fc1 (+GELU, half out)                   MODE 3: fc2 (+res, f32 out)
// Block 128x128xBK32(half), 8 warps (2Mx4N), double-buffered smem 32KB.
template<int KDIM, int NCOLS, int MODE>
__global__ void __launch_bounds__(256, 2) gemm_mma(
    const __half* __restrict__ A, const __half* __restrict__ Bw,
    const float* __restrict__ bias, const float* __restrict__ res,
    float* __restrict__ CoutF, __half* __restrict__ CoutH)
{
    extern __shared__ char sm[];
    const uint32_t smb = smem_u32(sm);
    const int t = threadIdx.x, lane = t & 31, warp = t >> 5;
    const int wm = warp & 1, wn = warp >> 1;
    const int m0 = blockIdx.y * 128, n0 = blockIdx.x * 128;
    constexpr int NC = KDIM / 32;

    const __half* aptr[2];
    const __half* bptr[2];
    uint32_t sA[2], sB[2];
    #pragma unroll
    for (int i = 0; i < 2; i++) {
        int idx = i * 256 + t;
        int row = idx >> 2, u = idx & 3;
        int gr = (MODE == 0) ? src_index(m0 + row) : (m0 + row);
        aptr[i] = A  + (size_t)gr * KDIM + u * 8;
        bptr[i] = Bw + (size_t)(n0 + row) * KDIM + u * 8;
        sA[i] = smb + SW64(row, u);
        sB[i] = smb + 16384 + SW64(row, u);
    }

    #pragma unroll
    for (int i = 0; i < 2; i++) {
        cp_async16(sA[i], aptr[i]);
        cp_async16(sB[i], bptr[i]);
    }
    CP_COMMIT();

    float acc[4][4][4];
    #pragma unroll
    for (int ms = 0; ms < 4; ms++)
        #pragma unroll
        for (int ns = 0; ns < 4; ns++)
            #pragma unroll
            for (int r = 0; r < 4; r++) acc[ms][ns][r] = 0.0f;

    for (int ch = 0; ch < NC; ch++) {
        const uint32_t bofs = (ch & 1) * 8192;
        if (ch + 1 < NC) {
            const uint32_t nofs = ((ch + 1) & 1) * 8192;
            #pragma unroll
            for (int i = 0; i < 2; i++) {
                cp_async16(sA[i] + nofs, aptr[i] + (ch + 1) * 32);
                cp_async16(sB[i] + nofs, bptr[i] + (ch + 1) * 32);
            }
            CP_COMMIT();
            CP_WAIT(1);
        } else {
            CP_WAIT(0);
        }
        __syncthreads();

        const uint32_t abase = smb + bofs;
        const uint32_t bbase = smb + 16384 + bofs;
        const int rlA = lane & 15;
        #pragma unroll
        for (int ks = 0; ks < 2; ks++) {
            uint32_t af[4][4];
            #pragma unroll
            for (int ms = 0; ms < 4; ms++) {
                int r = wm * 64 + ms * 16 + rlA;
                int u = 2 * ks + (lane >> 4);
                ldsm4(abase + SW64(r, u), af[ms][0], af[ms][1], af[ms][2], af[ms][3]);
            }
            uint32_t bf[4][2];
            #pragma unroll
            for (int ns = 0; ns < 4; ns++) {
                int r = wn * 32 + ns * 8 + (lane & 7);
                int u = 2 * ks + ((lane >> 3) & 1);
                ldsm2(bbase + SW64(r, u), bf[ns][0], bf[ns][1]);
            }
            #pragma unroll
            for (int ms = 0; ms < 4; ms++)
                #pragma unroll
                for (int ns = 0; ns < 4; ns++)
                    mma_f16(acc[ms][ns], af[ms][0], af[ms][1], af[ms][2], af[ms][3], bf[ns][0], bf[ns][1]);
        }
        __syncthreads();
    }

    const int g = lane >> 2, tig = lane & 3;
    #pragma unroll
    for (int ms = 0; ms < 4; ms++) {
        int row0 = m0 + wm * 64 + ms * 16 + g;
        int row1 = row0 + 8;
        int or0 = (MODE == 1) ? src_index(row0) : row0;
        int or1 = (MODE == 1) ? src_index(row1) : row1;
        #pragma unroll
        for (int ns = 0; ns < 4; ns++) {
            int col = n0 + wn * 32 + ns * 8 + 2 * tig;
            float bx = bias[col], by = bias[col + 1];
            float v0x = acc[ms][ns][0] + bx, v0y = acc[ms][ns][1] + by;
            float v1x = acc[ms][ns][2] + bx, v1y = acc[ms][ns][3] + by;
            if (MODE == 0) {
                // q-scale on first 256 cols
                float sc = (col < 256) ? 0.17677669529663687f : 1.0f;
                *reinterpret_cast<uint32_t*>(CoutH + (size_t)row0 * NCOLS + col) = pkh2(v0x * sc, v0y * sc);
                *reinterpret_cast<uint32_t*>(CoutH + (size_t)row1 * NCOLS + col) = pkh2(v1x * sc, v1y * sc);
            } else if (MODE == 1) {
                float2 r0 = *reinterpret_cast<const float2*>(res + (size_t)or0 * DIMC + col);
                float2 r1 = *reinterpret_cast<const float2*>(res + (size_t)or1 * DIMC + col);
                *reinterpret_cast<float2*>(CoutF + (size_t)or0 * DIMC + col) = make_float2(v0x + r0.x, v0y + r0.y);
                *reinterpret_cast<float2*>(CoutF + (size_t)or1 * DIMC + col) = make_float2(v1x + r1.x, v1y + r1.y);
            } else if (MODE == 2) {
                v0x = 0.5f * v0x * (1.0f + erff(v0x * 0.70710678118654752f));
                v0y = 0.5f * v0y * (1.0f + erff(v0y * 0.70710678118654752f));
                v1x = 0.5f * v1x * (1.0f + erff(v1x * 0.70710678118654752f));
                v1y = 0.5f * v1y * (1.0f + erff(v1y * 0.70710678118654752f));
                *reinterpret_cast<uint32_t*>(CoutH + (size_t)row0 * NCOLS + col) = pkh2(v0x, v0y);
                *reinterpret_cast<uint32_t*>(CoutH + (size_t)row1 * NCOLS + col) = pkh2(v1x, v1y);
            } else {
                float2 r0 = *reinterpret_cast<const float2*>(res + (size_t)row0 * DIMC + col);
                float2 r1 = *reinterpret_cast<const float2*>(res + (size_t)row1 * DIMC + col);
                *reinterpret_cast<float2*>(CoutF + (size_t)row0 * NCOLS + col) = make_float2(v0x + r0.x, v0y + r0.y);
                *reinterpret_cast<float2*>(CoutF + (size_t)row1 * NCOLS + col) = make_float2(v1x + r1.x, v1y + r1.y);
            }
        }
    }
}

// ---------------- fp16 flash attention (cp.async, ldmatrix.trans V) --------
// smem: Q @0 (8K), K @8192 (16K), V @24576 (16K), P @40960 (16K), sid @57344 (1K)
constexpr int Q_OFF   = 0;
constexpr int K_OFF   = 8192;
constexpr int V_OFF   = 24576;
constexpr int P_OFF   = 40960;
constexpr int SID_OFF = 57344;
constexpr int ATTN_SMEM = 58368;

__global__ void __launch_bounds__(256, 2) attn_tc(
    const __half* __restrict__ qkv, const __half* __restrict__ biasT,
    __half* __restrict__ out)
{
    extern __shared__ char sm[];
    const uint32_t smb = smem_u32(sm);
    const int wi = blockIdx.x, h = blockIdx.y, qt = blockIdx.z;
    const int t = threadIdx.x, lane = t & 31, w = t >> 5;
    const __half* base = qkv + (size_t)wi * WTOK * 768;
    int* sid = reinterpret_cast<int*>(sm + SID_OFF);

    sid[t] = region_id(wi, t);

    // Q (128x32 half, pre-scaled): 512 x 16B
    #pragma unroll
    for (int i = 0; i < 2; i++) {
        int idx = i * 256 + t;
        int row = idx >> 2, u = idx & 3;
        cp_async16(smb + Q_OFF + SW64(row, u),
                   base + (size_t)(qt * 128 + row) * 768 + h * 32 + u * 8);
    }
    // K (256x32): 1024 x 16B
    #pragma unroll
    for (int i = 0; i < 4; i++) {
        int idx = i * 256 + t;
        int row = idx >> 2, u = idx & 3;
        cp_async16(smb + K_OFF + SW64(row, u),
                   base + (size_t)row * 768 + 256 + h * 32 + u * 8);
    }
    // V (256x32): 1024 x 16B
    #pragma unroll
    for (int i = 0; i < 4; i++) {
        int idx = i * 256 + t;
        int row = idx >> 2, u = idx & 3;
        cp_async16(smb + V_OFF + SW64(row, u),
                   base + (size_t)row * 768 + 512 + h * 32 + u * 8);
    }
    CP_COMMIT();
    CP_WAIT(0);
    __syncthreads();

    // Q A-fragments (fixed per warp)
    const int rlA = lane & 15;
    uint32_t af[2][4];
    #pragma unroll
    for (int ks = 0; ks < 2; ks++) {
        int r = w * 16 + rlA;
        int u = 2 * ks + (lane >> 4);
        ldsm4(smb + Q_OFF + SW64(r, u), af[ks][0], af[ks][1], af[ks][2], af[ks][3]);
    }

    const int g = lane >> 2, tig = lane & 3;
    const int qr = qt * 128 + w * 16 + g;
    const __half* bT = biasT + (size_t)h * 65536;
    const int idq0 = sid[qr], idq1 = sid[qr + 8];

    float m0v = -1e30f, m1v = -1e30f, l0 = 0.0f, l1 = 0.0f;
    float oacc[4][4];
    #pragma unroll
    for (int dt = 0; dt < 4; dt++)
        #pragma unroll
        for (int r = 0; r < 4; r++) oacc[dt][r] = 0.0f;

    for (int ch = 0; ch < 4; ch++) {
        // ---- S = Q @ K_chunk^T ----
        float sacc[8][4];
        #pragma unroll
        for (int nt = 0; nt < 8; nt++)
            #pragma unroll
            for (int r = 0; r < 4; r++) sacc[nt][r] = 0.0f;

        #pragma unroll
        for (int ks = 0; ks < 2; ks++) {
            #pragma unroll
            for (int nt = 0; nt < 8; nt++) {
                uint32_t b0, b1;
                int r = ch * 64 + nt * 8 + (lane & 7);
                int u = 2 * ks + ((lane >> 3) & 1);
                ldsm2(smb + K_OFF + SW64(r, u), b0, b1);
                mma_f16(sacc[nt], af[ks][0], af[ks][1], af[ks][2], af[ks][3], b0, b1);
            }
        }

        // ---- bias + analytic mask, rowmax ----
        float mx0 = -1e30f, mx1 = -1e30f;
        #pragma unroll
        for (int nt = 0; nt < 8; nt++) {
            int mc = ch * 64 + nt * 8 + 2 * tig;
            int2 ids = *reinterpret_cast<const int2*>(sid + mc);
            float mk00 = (idq0 == ids.x) ? 0.0f : -100.0f;
            float mk01 = (idq0 == ids.y) ? 0.0f : -100.0f;
            float mk10 = (idq1 == ids.x) ? 0.0f : -100.0f;
            float mk11 = (idq1 == ids.y) ? 0.0f : -100.0f;
            size_t i0 = (size_t)qr * 256 + mc;
            size_t i1 = i0 + 8 * 256;
            float2 b0 = __half22float2(*reinterpret_cast<const __half2*>(bT + i0));
            float2 b1 = __half22float2(*reinterpret_cast<const __half2*>(bT + i1));
            sacc[nt][0] += b0.x + mk00; sacc[nt][1] += b0.y + mk01;
            sacc[nt][2] += b1.x + mk10; sacc[nt][3] += b1.y + mk11;
            mx0 = fmaxf(mx0, fmaxf(sacc[nt][0], sacc[nt][1]));
            mx1 = fmaxf(mx1, fmaxf(sacc[nt][2], sacc[nt][3]));
        }
        #pragma unroll
        for (int o = 1; o <= 2; o <<= 1) {
            mx0 = fmaxf(mx0, __shfl_xor_sync(0xffffffffu, mx0, o));
            mx1 = fmaxf(mx1, __shfl_xor_sync(0xffffffffu, mx1, o));
        }
        float nm0 = fmaxf(m0v, mx0), nm1 = fmaxf(m1v, mx1);
        float sc0 = __expf(m0v - nm0), sc1 = __expf(m1v - nm1);
        m0v = nm0; m1v = nm1;
        #pragma unroll
        for (int dt = 0; dt < 4; dt++) {
            oacc[dt][0] *= sc0; oacc[dt][1] *= sc0;
            oacc[dt][2] *= sc1; oacc[dt][3] *= sc1;
        }
        float s0 = 0.0f, s1 = 0.0f;
        #pragma unroll
        for (int nt = 0; nt < 8; nt++) {
            sacc[nt][0] = __expf(sacc[nt][0] - nm0);
            sacc[nt][1] = __expf(sacc[nt][1] - nm0);
            sacc[nt][2] = __expf(sacc[nt][2] - nm1);
            sacc[nt][3] = __expf(sacc[nt][3] - nm1);
            s0 += sacc[nt][0] + sacc[nt][1];
            s1 += sacc[nt][2] + sacc[nt][3];
        }
        #pragma unroll
        for (int o = 1; o <= 2; o <<= 1) {
            s0 += __shfl_xor_sync(0xffffffffu, s0, o);
            s1 += __shfl_xor_sync(0xffffffffu, s1, o);
        }
        l0 = l0 * sc0 + s0;
        l1 = l1 * sc1 + s1;

        // ---- store P (half): 16 rows x 64 halves, pitch 128B ----
        const uint32_t wbase = smb + P_OFF + w * 2048;
        #pragma unroll
        for (int nt = 0; nt < 8; nt++) {
            uint32_t h01 = pkh2(sacc[nt][0], sacc[nt][1]);
            uint32_t h23 = pkh2(sacc[nt][2], sacc[nt][3]);
            uint32_t a0 = wbase + g * 128 + ((nt ^ (g & 7)) << 4) + tig * 4;
            asm volatile("st.shared.b32 [%0], %1;" :: "r"(a0), "r"(h01));
            asm volatile("st.shared.b32 [%0], %1;" :: "r"(a0 + 8 * 128), "r"(h23));
        }
        __syncwarp();

        // ---- O += P_chunk @ V_chunk (V via ldmatrix.trans) ----
        #pragma unroll
        for (int ks = 0; ks < 4; ks++) {
            uint32_t pf[4];
            {
                int u = 2 * ks + (lane >> 4);
                ldsm4(wbase + rlA * 128 + ((u ^ (rlA & 7)) << 4), pf[0], pf[1], pf[2], pf[3]);
            }
            int key = ch * 64 + ks * 16 + (lane & 7) + 8 * ((lane >> 3) & 1);
            const uint32_t vrow = smb + V_OFF + key * 64;
            const int ksw = (key >> 1) & 3;
            #pragma unroll
            for (int dt = 0; dt < 4; dt++) {
                uint32_t b0, b1;
                ldsm2t(vrow + ((dt ^ ksw) << 4), b0, b1);
                mma_f16(oacc[dt], pf[0], pf[1], pf[2], pf[3], b0, b1);
            }
        }
        __syncwarp();
    }

    // ---- finalize (half out) ----
    float inv0 = 1.0f / l0, inv1 = 1.0f / l1;
    int qg = wi * 256 + qr;
    #pragma unroll
    for (int dt = 0; dt < 4; dt++) {
        int col = h * 32 + dt * 8 + 2 * tig;
        *reinterpret_cast<uint32_t*>(out + (size_t)qg * 256 + col) = pkh2(oacc[dt][0] * inv0, oacc[dt][1] * inv0);
        *reinterpret_cast<uint32_t*>(out + (size_t)(qg + 8) * 256 + col) = pkh2(oacc[dt][2] * inv1, oacc[dt][3] * inv1);
    }
}

// ---------------- launch ----------------
extern "C" void kernel_launch(void* const* d_in, const int* in_sizes, int n_in,
                              void* d_out, int out_size)
{
    const float* x          = (const float*)d_in[0];
    const float* g1         = (const float*)d_in[1];
    const float* b1         = (const float*)d_in[2];
    const float* qkv_w      = (const float*)d_in[3];
    const float* qkv_b      = (const float*)d_in[4];
    const float* bias_table = (const float*)d_in[5];
    const float* proj_w     = (const float*)d_in[6];
    const float* proj_b     = (const float*)d_in[7];
    const float* g2         = (const float*)d_in[8];
    const float* b2         = (const float*)d_in[9];
    const float* fc1_w      = (const float*)d_in[10];
    const float* fc1_b      = (const float*)d_in[11];
    const float* fc2_w      = (const float*)d_in[12];
    const float* fc2_b      = (const float*)d_in[13];
    const int*   rel_index  = (const int*)d_in[15];
    float* out = (float*)d_out;

    __half *p_lnh, *p_qkvh, *p_attnh, *p_mlph, *p_bias, *p_wq, *p_wp, *p_w1, *p_w2;
    float  *p_x2;
    cudaGetSymbolAddress((void**)&p_lnh,   g_lnh);
    cudaGetSymbolAddress((void**)&p_qkvh,  g_qkvh);
    cudaGetSymbolAddress((void**)&p_attnh, g_attnh);
    cudaGetSymbolAddress((void**)&p_mlph,  g_mlph);
    cudaGetSymbolAddress((void**)&p_x2,    g_x2);
    cudaGetSymbolAddress((void**)&p_bias,  g_bias);
    cudaGetSymbolAddress((void**)&p_wq,    g_wq);
    cudaGetSymbolAddress((void**)&p_wp,    g_wp);
    cudaGetSymbolAddress((void**)&p_w1,    g_w1);
    cudaGetSymbolAddress((void**)&p_w2,    g_w2);

    const int GEMM_SMEM = 32768;
    cudaFuncSetAttribute((const void*)gemm_mma<256, 768, 0>,  cudaFuncAttributeMaxDynamicSharedMemorySize, GEMM_SMEM);
    cudaFuncSetAttribute((const void*)gemm_mma<256, 256, 1>,  cudaFuncAttributeMaxDynamicSharedMemorySize, GEMM_SMEM);
    cudaFuncSetAttribute((const void*)gemm_mma<256, 1024, 2>, cudaFuncAttributeMaxDynamicSharedMemorySize, GEMM_SMEM);
    cudaFuncSetAttribute((const void*)gemm_mma<1024, 256, 3>, cudaFuncAttributeMaxDynamicSharedMemorySize, GEMM_SMEM);
    cudaFuncSetAttribute(attn_tc, cudaFuncAttributeMaxDynamicSharedMemorySize, ATTN_SMEM);

    // weight conversion + bias gather
    f2h_kernel<<<(768 * 256 / 4 + 255) / 256, 256>>>(qkv_w, p_wq, 768 * 256);
    f2h_kernel<<<(256 * 256 / 4 + 255) / 256, 256>>>(proj_w, p_wp, 256 * 256);
    f2h_kernel<<<(1024 * 256 / 4 + 255) / 256, 256>>>(fc1_w, p_w1, 1024 * 256);
    f2h_kernel<<<(256 * 1024 / 4 + 255) / 256, 256>>>(fc2_w, p_w2, 256 * 1024);
    biasT_kernel<<<256, 256>>>(bias_table, rel_index, p_bias);

    ln_kernel<<<M_TOK, 256>>>(x, g1, b1, p_lnh);
    gemm_mma<256, 768, 0><<<dim3(6, 512), 256, GEMM_SMEM>>>(p_lnh, p_wq, qkv_b, nullptr, nullptr, p_qkvh);
    attn_tc<<<dim3(NWIN, NHEAD, 2), 256, ATTN_SMEM>>>(p_qkvh, p_bias, p_attnh);
    gemm_mma<256, 256, 1><<<dim3(2, 512), 256, GEMM_SMEM>>>(p_attnh, p_wp, proj_b, x, p_x2, nullptr);
    ln_kernel<<<M_TOK, 256>>>(p_x2, g2, b2, p_lnh);
    gemm_mma<256, 1024, 2><<<dim3(8, 512), 256, GEMM_SMEM>>>(p_lnh, p_w1, fc1_b, nullptr, nullptr, p_mlph);
    gemm_mma<1024, 256, 3><<<dim3(2, 512), 256, GEMM_SMEM>>>(p_mlph, p_w2, fc2_b, p_x2, out, nullptr);
}

// round 7
// speedup vs baseline: 7.4811x; 1.2111x over previous
#include <cuda_runtime.h>
#include <cuda_fp16.h>
#include <cstdint>
#include <math.h>

// Problem constants
constexpr int M_TOK  = 65536;
constexpr int DIMC   = 256;
constexpr int NHEAD  = 8;
constexpr int HIDDEN = 1024;
constexpr int NWIN   = 256;
constexpr int WTOK   = 256;

// Scratch (half activation pipeline)
__device__ __half g_lnh [(size_t)M_TOK * DIMC];
__device__ __half g_qkvh[(size_t)M_TOK * 3 * DIMC];
__device__ __half g_attnh[(size_t)M_TOK * DIMC];
__device__ __half g_mlph[(size_t)M_TOK * HIDDEN];
__device__ float  g_x2  [(size_t)M_TOK * DIMC];
__device__ __half g_bias[(size_t)NHEAD * WTOK * WTOK];   // biasT[h][n][m]
// half weights
__device__ __half g_wq[768 * 256];
__device__ __half g_wp[256 * 256];
__device__ __half g_w1[1024 * 256];
__device__ __half g_w2[256 * 1024];

// ---------------- helpers ----------------
__device__ __forceinline__ uint32_t smem_u32(const void* p) {
    uint32_t a;
    asm("{ .reg .u64 t; cvta.to.shared.u64 t, %1; cvt.u32.u64 %0, t; }" : "=r"(a) : "l"(p));
    return a;
}
__device__ __forceinline__ void cp_async16(uint32_t dst, const void* src) {
    asm volatile("cp.async.cg.shared.global [%0], [%1], 16;" :: "r"(dst), "l"(src));
}
#define CP_COMMIT() asm volatile("cp.async.commit_group;")
#define CP_WAIT(n)  asm volatile("cp.async.wait_group %0;" :: "n"(n))
__device__ __forceinline__ void ldsm4(uint32_t addr, uint32_t& r0, uint32_t& r1, uint32_t& r2, uint32_t& r3) {
    asm volatile("ldmatrix.sync.aligned.m8n8.x4.shared.b16 {%0,%1,%2,%3}, [%4];"
                 : "=r"(r0), "=r"(r1), "=r"(r2), "=r"(r3) : "r"(addr));
}
__device__ __forceinline__ void ldsm2(uint32_t addr, uint32_t& r0, uint32_t& r1) {
    asm volatile("ldmatrix.sync.aligned.m8n8.x2.shared.b16 {%0,%1}, [%2];"
                 : "=r"(r0), "=r"(r1) : "r"(addr));
}
__device__ __forceinline__ void ldsm2t(uint32_t addr, uint32_t& r0, uint32_t& r1) {
    asm volatile("ldmatrix.sync.aligned.m8n8.x2.trans.shared.b16 {%0,%1}, [%2];"
                 : "=r"(r0), "=r"(r1) : "r"(addr));
}
__device__ __forceinline__ void mma_f16(float c[4], uint32_t a0, uint32_t a1, uint32_t a2, uint32_t a3,
                                        uint32_t b0, uint32_t b1) {
    asm volatile("mma.sync.aligned.m16n8k16.row.col.f32.f16.f16.f32 "
                 "{%0,%1,%2,%3}, {%4,%5,%6,%7}, {%8,%9}, {%0,%1,%2,%3};"
                 : "+f"(c[0]), "+f"(c[1]), "+f"(c[2]), "+f"(c[3])
                 : "r"(a0), "r"(a1), "r"(a2), "r"(a3), "r"(b0), "r"(b1));
}
__device__ __forceinline__ uint32_t pkh2(float a, float b) {
    __half2 h = __floats2half2_rn(a, b);
    return *reinterpret_cast<uint32_t*>(&h);
}

// roll(-2)+window-partition row map
__device__ __forceinline__ int src_index(int r) {
    int wi = r >> 8, pos = r & 255;
    int h1 = (wi >> 6) & 3, w1 = (wi >> 4) & 3, h2 = (wi >> 2) & 3, w2 = wi & 3;
    int a  = (pos >> 6) & 3, b  = (pos >> 4) & 3, c  = (pos >> 2) & 3, d  = pos & 3;
    int A_ = (h1 * 4 + a + 2) & 15;
    int B_ = (w1 * 4 + b + 2) & 15;
    int C_ = (h2 * 4 + c + 2) & 15;
    int D_ = (w2 * 4 + d + 2) & 15;
    return ((A_ * 16 + B_) * 16 + C_) * 16 + D_;
}
__device__ __forceinline__ int cls3(int c) { return (c < 12) ? 0 : ((c < 14) ? 1 : 2); }
__device__ __forceinline__ int region_id(int wi, int pos) {
    int cA = cls3(((wi >> 6) & 3) * 4 + ((pos >> 6) & 3));
    int cB = cls3(((wi >> 4) & 3) * 4 + ((pos >> 4) & 3));
    int cC = cls3(((wi >> 2) & 3) * 4 + ((pos >> 2) & 3));
    int cD = cls3((wi & 3) * 4 + (pos & 3));
    return ((cA * 3 + cB) * 3 + cC) * 3 + cD;
}

// ---------------- merged weight conversion ----------------
__global__ void __launch_bounds__(256) prep_weights(
    const float* __restrict__ wq, const float* __restrict__ wp,
    const float* __restrict__ w1, const float* __restrict__ w2,
    __half* __restrict__ oq, __half* __restrict__ op,
    __half* __restrict__ o1, __half* __restrict__ o2)
{
    int i = (blockIdx.x * 256 + threadIdx.x) * 4;
    const float* s; __half* d; int off;
    if (i < 196608)      { s = wq; d = oq; off = 0; }
    else if (i < 262144) { s = wp; d = op; off = 196608; }
    else if (i < 524288) { s = w1; d = o1; off = 262144; }
    else                 { s = w2; d = o2; off = 524288; }
    int j = i - off;
    float4 v = *reinterpret_cast<const float4*>(s + j);
    uint2 o;
    o.x = pkh2(v.x, v.y);
    o.y = pkh2(v.z, v.w);
    *reinterpret_cast<uint2*>(d + j) = o;
}

// ---------------- LayerNorm: warp-per-row, 8 rows/block ----------------
__global__ void __launch_bounds__(256) ln_kernel(
    const float* __restrict__ x, const float* __restrict__ g,
    const float* __restrict__ b, __half* __restrict__ out)
{
    int lane = threadIdx.x & 31, w = threadIdx.x >> 5;
    int row = blockIdx.x * 8 + w;
    const float* rp = x + (size_t)row * DIMC + lane * 8;
    float4 v0 = *reinterpret_cast<const float4*>(rp);
    float4 v1 = *reinterpret_cast<const float4*>(rp + 4);
    float s = v0.x + v0.y + v0.z + v0.w + v1.x + v1.y + v1.z + v1.w;
    #pragma unroll
    for (int o = 16; o; o >>= 1) s += __shfl_xor_sync(0xffffffffu, s, o);
    float mu = s * (1.0f / DIMC);
    float d0 = v0.x - mu, d1 = v0.y - mu, d2 = v0.z - mu, d3 = v0.w - mu;
    float d4 = v1.x - mu, d5 = v1.y - mu, d6 = v1.z - mu, d7 = v1.w - mu;
    float q = d0*d0 + d1*d1 + d2*d2 + d3*d3 + d4*d4 + d5*d5 + d6*d6 + d7*d7;
    #pragma unroll
    for (int o = 16; o; o >>= 1) q += __shfl_xor_sync(0xffffffffu, q, o);
    float rstd = rsqrtf(q * (1.0f / DIMC) + 1e-5f);
    const float* gp = g + lane * 8;
    const float* bp = b + lane * 8;
    float4 g0 = *reinterpret_cast<const float4*>(gp);
    float4 g1 = *reinterpret_cast<const float4*>(gp + 4);
    float4 b0 = *reinterpret_cast<const float4*>(bp);
    float4 b1 = *reinterpret_cast<const float4*>(bp + 4);
    uint4 o;
    o.x = pkh2(d0 * rstd * g0.x + b0.x, d1 * rstd * g0.y + b0.y);
    o.y = pkh2(d2 * rstd * g0.z + b0.z, d3 * rstd * g0.w + b0.w);
    o.z = pkh2(d4 * rstd * g1.x + b1.x, d5 * rstd * g1.y + b1.y);
    o.w = pkh2(d6 * rstd * g1.z + b1.z, d7 * rstd * g1.w + b1.w);
    *reinterpret_cast<uint4*>(out + (size_t)row * DIMC + lane * 8) = o;
}

// ---------------- biasT gather ----------------
__global__ void __launch_bounds__(256) biasT_kernel(
    const float* __restrict__ table, const int* __restrict__ rel, __half* __restrict__ biasT)
{
    int nm = blockIdx.x * 256 + threadIdx.x;
    int ri = rel[nm];
    #pragma unroll
    for (int h = 0; h < 8; h++)
        biasT[(size_t)h * 65536 + nm] = __float2half(table[ri * 8 + h]);
}

// smem swizzles
#define SW64(r, u)  ((r) * 64  + (((u) ^ (((r) >> 1) & 3)) << 4))   // 64B pitch, u 0..3
#define SW128(r, u) ((r) * 128 + (((u) ^ ((r) & 7)) << 4))          // 128B pitch, u 0..7

// ---------------- fp16 mma GEMM, BK=64, double-buffered ----------------
// MODE 0: QKV (gather, q-scale, half out)  MODE 1: proj (scatter+res, f32 out)
// MODE 2: fc1 (+GELU, half out)            MODE 3: fc2 (+res, f32 out)
template<int KDIM, int NCOLS, int MODE>
__global__ void __launch_bounds__(256, 2) gemm_mma(
    const __half* __restrict__ A, const __half* __restrict__ Bw,
    const float* __restrict__ bias, const float* __restrict__ res,
    float* __restrict__ CoutF, __half* __restrict__ CoutH)
{
    extern __shared__ char sm[];
    const uint32_t smb = smem_u32(sm);
    const int t = threadIdx.x, lane = t & 31, warp = t >> 5;
    const int wm = warp & 1, wn = warp >> 1;
    const int m0 = blockIdx.y * 128, n0 = blockIdx.x * 128;
    constexpr int NC = KDIM / 64;

    const __half* aptr[4];
    const __half* bptr[4];
    uint32_t sA[4], sB[4];
    #pragma unroll
    for (int i = 0; i < 4; i++) {
        int idx = i * 256 + t;
        int row = idx >> 3, u = idx & 7;
        int gr = (MODE == 0) ? src_index(m0 + row) : (m0 + row);
        aptr[i] = A  + (size_t)gr * KDIM + u * 8;
        bptr[i] = Bw + (size_t)(n0 + row) * KDIM + u * 8;
        sA[i] = smb + SW128(row, u);
        sB[i] = smb + 32768 + SW128(row, u);
    }

    #pragma unroll
    for (int i = 0; i < 4; i++) {
        cp_async16(sA[i], aptr[i]);
        cp_async16(sB[i], bptr[i]);
    }
    CP_COMMIT();

    float acc[4][4][4];
    #pragma unroll
    for (int ms = 0; ms < 4; ms++)
        #pragma unroll
        for (int ns = 0; ns < 4; ns++)
            #pragma unroll
            for (int r = 0; r < 4; r++) acc[ms][ns][r] = 0.0f;

    for (int ch = 0; ch < NC; ch++) {
        const uint32_t bofs = (ch & 1) * 16384;
        if (ch + 1 < NC) {
            const uint32_t nofs = ((ch + 1) & 1) * 16384;
            #pragma unroll
            for (int i = 0; i < 4; i++) {
                cp_async16(sA[i] + nofs, aptr[i] + (ch + 1) * 64);
                cp_async16(sB[i] + nofs, bptr[i] + (ch + 1) * 64);
            }
            CP_COMMIT();
            CP_WAIT(1);
        } else {
            CP_WAIT(0);
        }
        __syncthreads();

        const uint32_t abase = smb + bofs;
        const uint32_t bbase = smb + 32768 + bofs;
        const int rlA = lane & 15;
        #pragma unroll
        for (int ks = 0; ks < 4; ks++) {
            uint32_t af[4][4];
            #pragma unroll
            for (int ms = 0; ms < 4; ms++) {
                int r = wm * 64 + ms * 16 + rlA;
                int u = 2 * ks + (lane >> 4);
                ldsm4(abase + SW128(r, u), af[ms][0], af[ms][1], af[ms][2], af[ms][3]);
            }
            uint32_t bf[4][2];
            #pragma unroll
            for (int ns = 0; ns < 4; ns++) {
                int r = wn * 32 + ns * 8 + (lane & 7);
                int u = 2 * ks + ((lane >> 3) & 1);
                ldsm2(bbase + SW128(r, u), bf[ns][0], bf[ns][1]);
            }
            #pragma unroll
            for (int ms = 0; ms < 4; ms++)
                #pragma unroll
                for (int ns = 0; ns < 4; ns++)
                    mma_f16(acc[ms][ns], af[ms][0], af[ms][1], af[ms][2], af[ms][3], bf[ns][0], bf[ns][1]);
        }
        __syncthreads();
    }

    const int g = lane >> 2, tig = lane & 3;
    #pragma unroll
    for (int ms = 0; ms < 4; ms++) {
        int row0 = m0 + wm * 64 + ms * 16 + g;
        int row1 = row0 + 8;
        int or0 = (MODE == 1) ? src_index(row0) : row0;
        int or1 = (MODE == 1) ? src_index(row1) : row1;
        #pragma unroll
        for (int ns = 0; ns < 4; ns++) {
            int col = n0 + wn * 32 + ns * 8 + 2 * tig;
            float bx = bias[col], by = bias[col + 1];
            float v0x = acc[ms][ns][0] + bx, v0y = acc[ms][ns][1] + by;
            float v1x = acc[ms][ns][2] + bx, v1y = acc[ms][ns][3] + by;
            if (MODE == 0) {
                float sc = (col < 256) ? 0.17677669529663687f : 1.0f;
                *reinterpret_cast<uint32_t*>(CoutH + (size_t)row0 * NCOLS + col) = pkh2(v0x * sc, v0y * sc);
                *reinterpret_cast<uint32_t*>(CoutH + (size_t)row1 * NCOLS + col) = pkh2(v1x * sc, v1y * sc);
            } else if (MODE == 1) {
                float2 r0 = *reinterpret_cast<const float2*>(res + (size_t)or0 * DIMC + col);
                float2 r1 = *reinterpret_cast<const float2*>(res + (size_t)or1 * DIMC + col);
                *reinterpret_cast<float2*>(CoutF + (size_t)or0 * DIMC + col) = make_float2(v0x + r0.x, v0y + r0.y);
                *reinterpret_cast<float2*>(CoutF + (size_t)or1 * DIMC + col) = make_float2(v1x + r1.x, v1y + r1.y);
            } else if (MODE == 2) {
                v0x = 0.5f * v0x * (1.0f + erff(v0x * 0.70710678118654752f));
                v0y = 0.5f * v0y * (1.0f + erff(v0y * 0.70710678118654752f));
                v1x = 0.5f * v1x * (1.0f + erff(v1x * 0.70710678118654752f));
                v1y = 0.5f * v1y * (1.0f + erff(v1y * 0.70710678118654752f));
                *reinterpret_cast<uint32_t*>(CoutH + (size_t)row0 * NCOLS + col) = pkh2(v0x, v0y);
                *reinterpret_cast<uint32_t*>(CoutH + (size_t)row1 * NCOLS + col) = pkh2(v1x, v1y);
            } else {
                float2 r0 = *reinterpret_cast<const float2*>(res + (size_t)row0 * DIMC + col);
                float2 r1 = *reinterpret_cast<const float2*>(res + (size_t)row1 * DIMC + col);
                *reinterpret_cast<float2*>(CoutF + (size_t)row0 * NCOLS + col) = make_float2(v0x + r0.x, v0y + r0.y);
                *reinterpret_cast<float2*>(CoutF + (size_t)row1 * NCOLS + col) = make_float2(v1x + r1.x, v1y + r1.y);
            }
        }
    }
}

// ---------------- fp16 flash attention (register P pass-through) ----------
// smem: Q @0 (8K), K @8192 (16K), V @24576 (16K), sid @40960 (1K)
constexpr int Q_OFF   = 0;
constexpr int K_OFF   = 8192;
constexpr int V_OFF   = 24576;
constexpr int SID_OFF = 40960;
constexpr int ATTN_SMEM = 41984;

__global__ void __launch_bounds__(256, 2) attn_tc(
    const __half* __restrict__ qkv, const __half* __restrict__ biasT,
    __half* __restrict__ out)
{
    extern __shared__ char sm[];
    const uint32_t smb = smem_u32(sm);
    const int wi = blockIdx.x, h = blockIdx.y, qt = blockIdx.z;
    const int t = threadIdx.x, lane = t & 31, w = t >> 5;
    const __half* base = qkv + (size_t)wi * WTOK * 768;
    int* sid = reinterpret_cast<int*>(sm + SID_OFF);

    sid[t] = region_id(wi, t);

    #pragma unroll
    for (int i = 0; i < 2; i++) {
        int idx = i * 256 + t;
        int row = idx >> 2, u = idx & 3;
        cp_async16(smb + Q_OFF + SW64(row, u),
                   base + (size_t)(qt * 128 + row) * 768 + h * 32 + u * 8);
    }
    #pragma unroll
    for (int i = 0; i < 4; i++) {
        int idx = i * 256 + t;
        int row = idx >> 2, u = idx & 3;
        cp_async16(smb + K_OFF + SW64(row, u),
                   base + (size_t)row * 768 + 256 + h * 32 + u * 8);
    }
    #pragma unroll
    for (int i = 0; i < 4; i++) {
        int idx = i * 256 + t;
        int row = idx >> 2, u = idx & 3;
        cp_async16(smb + V_OFF + SW64(row, u),
                   base + (size_t)row * 768 + 512 + h * 32 + u * 8);
    }
    CP_COMMIT();
    CP_WAIT(0);
    __syncthreads();

    const int rlA = lane & 15;
    uint32_t af[2][4];
    #pragma unroll
    for (int ks = 0; ks < 2; ks++) {
        int r = w * 16 + rlA;
        int u = 2 * ks + (lane >> 4);
        ldsm4(smb + Q_OFF + SW64(r, u), af[ks][0], af[ks][1], af[ks][2], af[ks][3]);
    }

    const int g = lane >> 2, tig = lane & 3;
    const int qr = qt * 128 + w * 16 + g;
    const __half* bT = biasT + (size_t)h * 65536;
    const int idq0 = sid[qr], idq1 = sid[qr + 8];

    float m0v = -1e30f, m1v = -1e30f, l0 = 0.0f, l1 = 0.0f;
    float oacc[4][4];
    #pragma unroll
    for (int dt = 0; dt < 4; dt++)
        #pragma unroll
        for (int r = 0; r < 4; r++) oacc[dt][r] = 0.0f;

    for (int ch = 0; ch < 4; ch++) {
        // ---- S = Q @ K_chunk^T ----
        float sacc[8][4];
        #pragma unroll
        for (int nt = 0; nt < 8; nt++)
            #pragma unroll
            for (int r = 0; r < 4; r++) sacc[nt][r] = 0.0f;

        #pragma unroll
        for (int ks = 0; ks < 2; ks++) {
            #pragma unroll
            for (int nt = 0; nt < 8; nt++) {
                uint32_t b0, b1;
                int r = ch * 64 + nt * 8 + (lane & 7);
                int u = 2 * ks + ((lane >> 3) & 1);
                ldsm2(smb + K_OFF + SW64(r, u), b0, b1);
                mma_f16(sacc[nt], af[ks][0], af[ks][1], af[ks][2], af[ks][3], b0, b1);
            }
        }

        // ---- bias + analytic mask, rowmax ----
        float mx0 = -1e30f, mx1 = -1e30f;
        #pragma unroll
        for (int nt = 0; nt < 8; nt++) {
            int mc = ch * 64 + nt * 8 + 2 * tig;
            int2 ids = *reinterpret_cast<const int2*>(sid + mc);
            float mk00 = (idq0 == ids.x) ? 0.0f : -100.0f;
            float mk01 = (idq0 == ids.y) ? 0.0f : -100.0f;
            float mk10 = (idq1 == ids.x) ? 0.0f : -100.0f;
            float mk11 = (idq1 == ids.y) ? 0.0f : -100.0f;
            size_t i0 = (size_t)qr * 256 + mc;
            size_t i1 = i0 + 8 * 256;
            float2 b0 = __half22float2(*reinterpret_cast<const __half2*>(bT + i0));
            float2 b1 = __half22float2(*reinterpret_cast<const __half2*>(bT + i1));
            sacc[nt][0] += b0.x + mk00; sacc[nt][1] += b0.y + mk01;
            sacc[nt][2] += b1.x + mk10; sacc[nt][3] += b1.y + mk11;
            mx0 = fmaxf(mx0, fmaxf(sacc[nt][0], sacc[nt][1]));
            mx1 = fmaxf(mx1, fmaxf(sacc[nt][2], sacc[nt][3]));
        }
        #pragma unroll
        for (int o = 1; o <= 2; o <<= 1) {
            mx0 = fmaxf(mx0, __shfl_xor_sync(0xffffffffu, mx0, o));
            mx1 = fmaxf(mx1, __shfl_xor_sync(0xffffffffu, mx1, o));
        }
        float nm0 = fmaxf(m0v, mx0), nm1 = fmaxf(m1v, mx1);
        float sc0 = __expf(m0v - nm0), sc1 = __expf(m1v - nm1);
        m0v = nm0; m1v = nm1;
        #pragma unroll
        for (int dt = 0; dt < 4; dt++) {
            oacc[dt][0] *= sc0; oacc[dt][1] *= sc0;
            oacc[dt][2] *= sc1; oacc[dt][3] *= sc1;
        }
        float s0 = 0.0f, s1 = 0.0f;
        #pragma unroll
        for (int nt = 0; nt < 8; nt++) {
            sacc[nt][0] = __expf(sacc[nt][0] - nm0);
            sacc[nt][1] = __expf(sacc[nt][1] - nm0);
            sacc[nt][2] = __expf(sacc[nt][2] - nm1);
            sacc[nt][3] = __expf(sacc[nt][3] - nm1);
            s0 += sacc[nt][0] + sacc[nt][1];
            s1 += sacc[nt][2] + sacc[nt][3];
        }
        #pragma unroll
        for (int o = 1; o <= 2; o <<= 1) {
            s0 += __shfl_xor_sync(0xffffffffu, s0, o);
            s1 += __shfl_xor_sync(0xffffffffu, s1, o);
        }
        l0 = l0 * sc0 + s0;
        l1 = l1 * sc1 + s1;

        // ---- O += P @ V: P fragments straight from sacc registers ----
        #pragma unroll
        for (int ks = 0; ks < 4; ks++) {
            uint32_t pf0 = pkh2(sacc[2*ks][0],   sacc[2*ks][1]);
            uint32_t pf1 = pkh2(sacc[2*ks][2],   sacc[2*ks][3]);
            uint32_t pf2 = pkh2(sacc[2*ks+1][0], sacc[2*ks+1][1]);
            uint32_t pf3 = pkh2(sacc[2*ks+1][2], sacc[2*ks+1][3]);
            int key = ch * 64 + ks * 16 + (lane & 7) + 8 * ((lane >> 3) & 1);
            const uint32_t vrow = smb + V_OFF + key * 64;
            const int ksw = (key >> 1) & 3;
            #pragma unroll
            for (int dt = 0; dt < 4; dt++) {
                uint32_t b0, b1;
                ldsm2t(vrow + ((dt ^ ksw) << 4), b0, b1);
                mma_f16(oacc[dt], pf0, pf1, pf2, pf3, b0, b1);
            }
        }
    }

    // ---- finalize ----
    float inv0 = 1.0f / l0, inv1 = 1.0f / l1;
    int qg = wi * 256 + qr;
    #pragma unroll
    for (int dt = 0; dt < 4; dt++) {
        int col = h * 32 + dt * 8 + 2 * tig;
        *reinterpret_cast<uint32_t*>(out + (size_t)qg * 256 + col) = pkh2(oacc[dt][0] * inv0, oacc[dt][1] * inv0);
        *reinterpret_cast<uint32_t*>(out + (size_t)(qg + 8) * 256 + col) = pkh2(oacc[dt][2] * inv1, oacc[dt][3] * inv1);
    }
}

// ---------------- launch ----------------
extern "C" void kernel_launch(void* const* d_in, const int* in_sizes, int n_in,
                              void* d_out, int out_size)
{
    const float* x          = (const float*)d_in[0];
    const float* g1         = (const float*)d_in[1];
    const float* b1         = (const float*)d_in[2];
    const float* qkv_w      = (const float*)d_in[3];
    const float* qkv_b      = (const float*)d_in[4];
    const float* bias_table = (const float*)d_in[5];
    const float* proj_w     = (const float*)d_in[6];
    const float* proj_b     = (const float*)d_in[7];
    const float* g2         = (const float*)d_in[8];
    const float* b2         = (const float*)d_in[9];
    const float* fc1_w      = (const float*)d_in[10];
    const float* fc1_b      = (const float*)d_in[11];
    const float* fc2_w      = (const float*)d_in[12];
    const float* fc2_b      = (const float*)d_in[13];
    const int*   rel_index  = (const int*)d_in[15];
    float* out = (float*)d_out;

    __half *p_lnh, *p_qkvh, *p_attnh, *p_mlph, *p_bias, *p_wq, *p_wp, *p_w1, *p_w2;
    float  *p_x2;
    cudaGetSymbolAddress((void**)&p_lnh,   g_lnh);
    cudaGetSymbolAddress((void**)&p_qkvh,  g_qkvh);
    cudaGetSymbolAddress((void**)&p_attnh, g_attnh);
    cudaGetSymbolAddress((void**)&p_mlph,  g_mlph);
    cudaGetSymbolAddress((void**)&p_x2,    g_x2);
    cudaGetSymbolAddress((void**)&p_bias,  g_bias);
    cudaGetSymbolAddress((void**)&p_wq,    g_wq);
    cudaGetSymbolAddress((void**)&p_wp,    g_wp);
    cudaGetSymbolAddress((void**)&p_w1,    g_w1);
    cudaGetSymbolAddress((void**)&p_w2,    g_w2);

    const int GEMM_SMEM = 65536;
    cudaFuncSetAttribute((const void*)gemm_mma<256, 768, 0>,  cudaFuncAttributeMaxDynamicSharedMemorySize, GEMM_SMEM);
    cudaFuncSetAttribute((const void*)gemm_mma<256, 256, 1>,  cudaFuncAttributeMaxDynamicSharedMemorySize, GEMM_SMEM);
    cudaFuncSetAttribute((const void*)gemm_mma<256, 1024, 2>, cudaFuncAttributeMaxDynamicSharedMemorySize, GEMM_SMEM);
    cudaFuncSetAttribute((const void*)gemm_mma<1024, 256, 3>, cudaFuncAttributeMaxDynamicSharedMemorySize, GEMM_SMEM);
    cudaFuncSetAttribute(attn_tc, cudaFuncAttributeMaxDynamicSharedMemorySize, ATTN_SMEM);

    prep_weights<<<768, 256>>>(qkv_w, proj_w, fc1_w, fc2_w, p_wq, p_wp, p_w1, p_w2);
    biasT_kernel<<<256, 256>>>(bias_table, rel_index, p_bias);

    ln_kernel<<<8192, 256>>>(x, g1, b1, p_lnh);
    gemm_mma<256, 768, 0><<<dim3(6, 512), 256, GEMM_SMEM>>>(p_lnh, p_wq, qkv_b, nullptr, nullptr, p_qkvh);
    attn_tc<<<dim3(NWIN, NHEAD, 2), 256, ATTN_SMEM>>>(p_qkvh, p_bias, p_attnh);
    gemm_mma<256, 256, 1><<<dim3(2, 512), 256, GEMM_SMEM>>>(p_attnh, p_wp, proj_b, x, p_x2, nullptr);
    ln_kernel<<<8192, 256>>>(p_x2, g2, b2, p_lnh);
    gemm_mma<256, 1024, 2><<<dim3(8, 512), 256, GEMM_SMEM>>>(p_lnh, p_w1, fc1_b, nullptr, nullptr, p_mlph);
    gemm_mma<1024, 256, 3><<<dim3(2, 512), 256, GEMM_SMEM>>>(p_mlph, p_w2, fc2_b, p_x2, out, nullptr);
}